// round 1
// baseline (speedup 1.0000x reference)
#include <cuda_runtime.h>
#include <cstdint>

// ---------------- problem constants ----------------
#define kB   2
#define kN   16384
#define kDIM 512
#define kH   8
#define kD   64
#define kM   64
#define kSC  64
#define kROWS   (kB * kN)        // 32768
#define kRH     (kB * kH * kN)   // 262144 (row-heads)
#define kCHUNKS 64               // encode split-N chunks (256 keys each)
#define kBH     (kB * kH)        // 16

// ---------------- scratch (device globals; no allocation allowed) ----------------
__device__ float g_xmid[kROWS * kDIM];            // (b*N+n, h*64+d)  64 MB
__device__ float g_k[kBH * kN * kD];              // (b,h,n,d)        64 MB
__device__ float g_v[kBH * kN * kD];
__device__ float g_q[kBH * kN * kD];
__device__ float g_mix[kROWS * kDIM];             // (b,n,h*64+d)     64 MB
__device__ float g_kc[kBH * kSC * kD];
__device__ float g_vc[kBH * kSC * kD];
__device__ float g_psum[kCHUNKS * kBH * kM];
__device__ float g_pacc[kCHUNKS * kBH * kM * kD]; // 17 MB
__device__ float g_latent[kBH * kM * kD];

// ---------------- K_ctx: kc/vc = context @ Wck^T/Wcv^T + bias ----------------
__global__ __launch_bounds__(256) void ctx_proj(
    const float* __restrict__ context, const float* __restrict__ Wck,
    const float* __restrict__ bck, const float* __restrict__ Wcv,
    const float* __restrict__ bcv) {
  __shared__ float sctx[kSC * kD];
  int tid = threadIdx.x, bh = blockIdx.x;
  for (int idx = tid; idx < kSC * kD; idx += 256)
    sctx[idx] = context[(size_t)bh * kSC * kD + idx];
  __syncthreads();
  for (int t = tid; t < 2 * kSC * kD; t += 256) {
    int sel = t >> 12;            // 0 -> kc, 1 -> vc
    int r = t & 4095;
    int s = r >> 6, d = r & 63;
    const float* W = sel ? Wcv : Wck;
    float acc = sel ? bcv[d] : bck[d];
#pragma unroll 8
    for (int c = 0; c < 64; c++) acc += sctx[s * 64 + c] * W[d * 64 + c];
    (sel ? g_vc : g_kc)[(size_t)bh * 4096 + s * 64 + d] = acc;
  }
}

// ---------------- SGEMM: C[r,c] = bias[c] + sum_k A[r,k] * W[c,k] ----------------
// A: (Mrows x 512) row-major, W: (512 x 512) row-major [out][in], cols = 512.
// Tile 128x128, BK=8, 256 threads, 8x8 micro-tile.
__global__ __launch_bounds__(256) void sgemm512(
    const float* __restrict__ A, const float* __restrict__ W,
    const float* __restrict__ bias, float* __restrict__ C) {
  __shared__ float As[8][128];
  __shared__ float Bs[8][128];
  int tid = threadIdx.x;
  int tx = tid & 15, ty = tid >> 4;
  size_t br = (size_t)blockIdx.x * 128;
  int bc = blockIdx.y * 128;
  float acc[8][8];
#pragma unroll
  for (int i = 0; i < 8; i++)
#pragma unroll
    for (int j = 0; j < 8; j++) acc[i][j] = 0.f;

  int lr = tid >> 1;
  int lk = (tid & 1) * 4;
  const float* Ap = A + (br + lr) * 512 + lk;
  const float* Wp = W + (size_t)(bc + lr) * 512 + lk;

  for (int k0 = 0; k0 < 512; k0 += 8) {
    float4 a4 = *(const float4*)(Ap + k0);
    float4 w4 = *(const float4*)(Wp + k0);
    __syncthreads();
    As[lk + 0][lr] = a4.x; As[lk + 1][lr] = a4.y;
    As[lk + 2][lr] = a4.z; As[lk + 3][lr] = a4.w;
    Bs[lk + 0][lr] = w4.x; Bs[lk + 1][lr] = w4.y;
    Bs[lk + 2][lr] = w4.z; Bs[lk + 3][lr] = w4.w;
    __syncthreads();
#pragma unroll
    for (int kk = 0; kk < 8; kk++) {
      float4 a0 = *(const float4*)&As[kk][ty * 8];
      float4 a1 = *(const float4*)&As[kk][ty * 8 + 4];
      float4 w0 = *(const float4*)&Bs[kk][tx * 8];
      float4 w1 = *(const float4*)&Bs[kk][tx * 8 + 4];
      float ar[8] = {a0.x, a0.y, a0.z, a0.w, a1.x, a1.y, a1.z, a1.w};
      float wr[8] = {w0.x, w0.y, w0.z, w0.w, w1.x, w1.y, w1.z, w1.w};
#pragma unroll
      for (int i = 0; i < 8; i++)
#pragma unroll
        for (int j = 0; j < 8; j++) acc[i][j] += ar[i] * wr[j];
    }
  }
#pragma unroll
  for (int i = 0; i < 8; i++) {
    size_t row = br + ty * 8 + i;
#pragma unroll
    for (int j = 0; j < 8; j++)
      C[row * 512 + bc + tx * 8 + j] = acc[i][j] + bias[bc + tx * 8 + j];
  }
}

// ---------------- KVQ: per head-row 64-vec -> 192 outputs (k|v|q) ----------------
// Input g_xmid row bn, head h occupies cols h*64..h*64+63 (Wk/Wv/Wcq shared across heads).
// Each warp handles one bn (all 8 heads simultaneously, sharing smem W reads).
__global__ __launch_bounds__(256) void kvq_proj(
    const float* __restrict__ Wk, const float* __restrict__ bk,
    const float* __restrict__ Wv, const float* __restrict__ bv,
    const float* __restrict__ Wq, const float* __restrict__ bq) {
  __shared__ float sW[64 * 192];  // [in][col]; col 0..63 k, 64..127 v, 128..191 q
  int tid = threadIdx.x;
  for (int idx = tid; idx < 64 * 192; idx += 256) {
    int i = idx / 192, col = idx % 192;
    float w;
    if (col < 64)       w = Wk[col * 64 + i];
    else if (col < 128) w = Wv[(col - 64) * 64 + i];
    else                w = Wq[(col - 128) * 64 + i];
    sW[idx] = w;
  }
  __syncthreads();
  int warp = tid >> 5, lane = tid & 31;
  int bn = blockIdx.x * 8 + warp;  // token row (b*N+n)
  const float* xr = g_xmid + (size_t)bn * 512;
  float x0[8], x1[8];
#pragma unroll
  for (int h = 0; h < 8; h++) {
    x0[h] = xr[h * 64 + lane];
    x1[h] = xr[h * 64 + lane + 32];
  }
  float bias[6];
#pragma unroll
  for (int j = 0; j < 6; j++) {
    int col = lane + 32 * j;
    bias[j] = (col < 64) ? bk[col] : (col < 128) ? bv[col - 64] : bq[col - 128];
  }
  float acc[8][6];
#pragma unroll
  for (int h = 0; h < 8; h++)
#pragma unroll
    for (int j = 0; j < 6; j++) acc[h][j] = bias[j];

#pragma unroll 8
  for (int i = 0; i < 64; i++) {
    float wv[6];
#pragma unroll
    for (int j = 0; j < 6; j++) wv[j] = sW[i * 192 + lane + 32 * j];
#pragma unroll
    for (int h = 0; h < 8; h++) {
      float xv = __shfl_sync(0xffffffffu, (i < 32) ? x0[h] : x1[h], i & 31);
#pragma unroll
      for (int j = 0; j < 6; j++) acc[h][j] += xv * wv[j];
    }
  }
  int b = bn >> 14, n = bn & (kN - 1);
#pragma unroll
  for (int h = 0; h < 8; h++) {
    size_t dst = ((size_t)(b * kH + h) * kN + n) * 64;
    g_k[dst + lane]      = acc[h][0];
    g_k[dst + lane + 32] = acc[h][1];
    g_v[dst + lane]      = acc[h][2];
    g_v[dst + lane + 32] = acc[h][3];
    g_q[dst + lane]      = acc[h][4];
    g_q[dst + lane + 32] = acc[h][5];
  }
}

// ---------------- encode partial: per (chunk, bh) accumulate exp(qg.k) and exp*v ----------------
// No max-subtraction: logits ~ N(0,64), worst-case ~40 << 88 (fp32 exp range).
__global__ __launch_bounds__(256) void enc_partial(const float* __restrict__ qg) {
  __shared__ float sQ[64 * 65];
  __shared__ float sK[32 * 65];
  __shared__ float sV[32 * 68];
  __shared__ float sP[64 * 33];
  int tid = threadIdx.x;
  int c = blockIdx.x, bh = blockIdx.y;
  int h = bh & 7;
  for (int idx = tid; idx < 4096; idx += 256) {
    int m = idx >> 6, d = idx & 63;
    sQ[m * 65 + d] = qg[(h * 64 + m) * 64 + d];
  }
  int m_t = tid >> 2, quad = tid & 3, d0 = quad * 16;
  float acc[16];
#pragma unroll
  for (int j = 0; j < 16; j++) acc[j] = 0.f;
  float lsum = 0.f;
  int base = bh * kN + c * 256;
  for (int nt = 0; nt < 8; nt++) {
    __syncthreads();
    for (int idx = tid; idx < 2048; idx += 256) {
      int r = idx >> 6, d = idx & 63;
      size_t src = (size_t)(base + nt * 32 + r) * 64 + d;
      sK[r * 65 + d] = g_k[src];
      sV[r * 68 + d] = g_v[src];
    }
    __syncthreads();
    float dot[8];
#pragma unroll
    for (int ii = 0; ii < 8; ii++) dot[ii] = 0.f;
#pragma unroll 8
    for (int i = 0; i < 64; i++) {
      float qv = sQ[m_t * 65 + i];
#pragma unroll
      for (int ii = 0; ii < 8; ii++)
        dot[ii] += qv * sK[(quad * 8 + ii) * 65 + i];
    }
#pragma unroll
    for (int ii = 0; ii < 8; ii++) {
      float e = __expf(dot[ii]);
      sP[m_t * 33 + quad * 8 + ii] = e;
      lsum += e;
    }
    __syncthreads();
#pragma unroll 4
    for (int np = 0; np < 32; np++) {
      float p = sP[m_t * 33 + np];
      const float* vrow = sV + np * 68 + d0;
#pragma unroll
      for (int j = 0; j < 16; j++) acc[j] += p * vrow[j];
    }
  }
  lsum += __shfl_xor_sync(0xffffffffu, lsum, 1);
  lsum += __shfl_xor_sync(0xffffffffu, lsum, 2);
  size_t ob = (size_t)(c * kBH + bh) * 64 + m_t;
  if (quad == 0) g_psum[ob] = lsum;
#pragma unroll
  for (int j = 0; j < 16; j++) g_pacc[ob * 64 + d0 + j] = acc[j];
}

// ---------------- encode reduce: latent = sum_c pacc / sum_c psum ----------------
__global__ __launch_bounds__(256) void enc_reduce() {
  __shared__ float sinv[64];
  int tid = threadIdx.x, bh = blockIdx.x;
  if (tid < 64) {
    float s = 0.f;
    for (int c = 0; c < kCHUNKS; c++)
      s += g_psum[(size_t)(c * kBH + bh) * 64 + tid];
    sinv[tid] = 1.f / s;
  }
  __syncthreads();
  for (int idx = tid; idx < 4096; idx += 256) {
    int m = idx >> 6, d = idx & 63;
    float s = 0.f;
    for (int c = 0; c < kCHUNKS; c++)
      s += g_pacc[((size_t)(c * kBH + bh) * 64 + m) * 64 + d];
    g_latent[(size_t)bh * 4096 + m * 64 + d] = s * sinv[m];
  }
}

// ---------------- decode (self path): per token softmax(k.qg) @ latent -> g_mix ----------------
__global__ __launch_bounds__(256) void dec_self(const float* __restrict__ qg) {
  __shared__ float sQg[64 * 65];
  __shared__ float sLat[64 * 65];
  int tid = threadIdx.x;
  int bh = blockIdx.y, h = bh & 7, b = bh >> 3;
  for (int idx = tid; idx < 4096; idx += 256) {
    int m = idx >> 6, d = idx & 63;
    sQg[m * 65 + d] = qg[(h * 64 + m) * 64 + d];
    sLat[m * 65 + d] = g_latent[(size_t)bh * 4096 + idx];
  }
  __syncthreads();
  int warp = tid >> 5, lane = tid & 31;
  int n0 = blockIdx.x * 64 + warp * 8;
  for (int r = 0; r < 8; r++) {
    int n = n0 + r;
    const float* kp = g_k + ((size_t)bh * kN + n) * 64;
    float k0 = kp[lane], k1 = kp[lane + 32];
    float s0 = 0.f, s1 = 0.f;
#pragma unroll 8
    for (int d = 0; d < 64; d++) {
      float kv = __shfl_sync(0xffffffffu, (d < 32) ? k0 : k1, d & 31);
      s0 += kv * sQg[lane * 65 + d];
      s1 += kv * sQg[(lane + 32) * 65 + d];
    }
    float e0 = __expf(s0), e1 = __expf(s1);
    float sum = e0 + e1;
#pragma unroll
    for (int o = 16; o > 0; o >>= 1) sum += __shfl_xor_sync(0xffffffffu, sum, o);
    float inv = 1.f / sum;
    float t0 = 0.f, t1 = 0.f;
#pragma unroll 8
    for (int m = 0; m < 64; m++) {
      float ev = __shfl_sync(0xffffffffu, (m < 32) ? e0 : e1, m & 31);
      t0 += ev * sLat[m * 65 + lane];
      t1 += ev * sLat[m * 65 + lane + 32];
    }
    float* op = g_mix + ((size_t)b * kN + n) * 512 + h * 64;
    op[lane] = t0 * inv;
    op[lane + 32] = t1 * inv;
  }
}

// ---------------- cross path + sigmoid gate: g_mix = w*self + (1-w)*cross ----------------
__global__ __launch_bounds__(256) void dec_cross(const float* __restrict__ smix) {
  __shared__ float sKc[64 * 65];
  __shared__ float sVc[64 * 65];
  int tid = threadIdx.x;
  int bh = blockIdx.y, h = bh & 7, b = bh >> 3;
  for (int idx = tid; idx < 4096; idx += 256) {
    int s = idx >> 6, d = idx & 63;
    sKc[s * 65 + d] = g_kc[(size_t)bh * 4096 + idx];
    sVc[s * 65 + d] = g_vc[(size_t)bh * 4096 + idx];
  }
  __syncthreads();
  float wmix = 1.f / (1.f + __expf(-smix[0]));
  int warp = tid >> 5, lane = tid & 31;
  int n0 = blockIdx.x * 64 + warp * 8;
  for (int r = 0; r < 8; r++) {
    int n = n0 + r;
    const float* qp = g_q + ((size_t)bh * kN + n) * 64;
    float q0 = qp[lane], q1 = qp[lane + 32];
    float s0 = 0.f, s1 = 0.f;
#pragma unroll 8
    for (int d = 0; d < 64; d++) {
      float qv = __shfl_sync(0xffffffffu, (d < 32) ? q0 : q1, d & 31);
      s0 += qv * sKc[lane * 65 + d];
      s1 += qv * sKc[(lane + 32) * 65 + d];
    }
    float e0 = __expf(s0), e1 = __expf(s1);
    float sum = e0 + e1;
#pragma unroll
    for (int o = 16; o > 0; o >>= 1) sum += __shfl_xor_sync(0xffffffffu, sum, o);
    float inv = 1.f / sum;
    float t0 = 0.f, t1 = 0.f;
#pragma unroll 8
    for (int s = 0; s < 64; s++) {
      float ev = __shfl_sync(0xffffffffu, (s < 32) ? e0 : e1, s & 31);
      t0 += ev * sVc[s * 65 + lane];
      t1 += ev * sVc[s * 65 + lane + 32];
    }
    float* op = g_mix + ((size_t)b * kN + n) * 512 + h * 64;
    op[lane]      = wmix * op[lane]      + (1.f - wmix) * t0 * inv;
    op[lane + 32] = wmix * op[lane + 32] + (1.f - wmix) * t1 * inv;
  }
}

// ---------------- launch ----------------
extern "C" void kernel_launch(void* const* d_in, const int* in_sizes, int n_in,
                              void* d_out, int out_size) {
  const float* x    = (const float*)d_in[0];
  const float* ctx  = (const float*)d_in[1];
  const float* qg   = (const float*)d_in[2];
  const float* Wx   = (const float*)d_in[3];
  const float* bx   = (const float*)d_in[4];
  const float* Wk   = (const float*)d_in[5];
  const float* bk   = (const float*)d_in[6];
  const float* Wv   = (const float*)d_in[7];
  const float* bv   = (const float*)d_in[8];
  const float* Wcq  = (const float*)d_in[9];
  const float* bcq  = (const float*)d_in[10];
  const float* Wck  = (const float*)d_in[11];
  const float* bck  = (const float*)d_in[12];
  const float* Wcv  = (const float*)d_in[13];
  const float* bcv  = (const float*)d_in[14];
  const float* smx  = (const float*)d_in[15];
  const float* Wo   = (const float*)d_in[16];
  const float* bo   = (const float*)d_in[17];
  float* out = (float*)d_out;

  void *xmid_p = nullptr, *mix_p = nullptr;
  cudaGetSymbolAddress(&xmid_p, g_xmid);
  cudaGetSymbolAddress(&mix_p, g_mix);

  ctx_proj<<<kBH, 256>>>(ctx, Wck, bck, Wcv, bcv);
  sgemm512<<<dim3(kROWS / 128, 4), 256>>>(x, Wx, bx, (float*)xmid_p);
  kvq_proj<<<kROWS / 8, 256>>>(Wk, bk, Wv, bv, Wcq, bcq);
  enc_partial<<<dim3(kCHUNKS, kBH), 256>>>(qg);
  enc_reduce<<<kBH, 256>>>();
  dec_self<<<dim3(kN / 64, kBH), 256>>>(qg);
  dec_cross<<<dim3(kN / 64, kBH), 256>>>(smx);
  sgemm512<<<dim3(kROWS / 128, 4), 256>>>((const float*)mix_p, Wo, bo, out);
}

// round 4
// speedup vs baseline: 1.0719x; 1.0719x over previous
#include <cuda_runtime.h>
#include <cuda_bf16.h>
#include <cstdint>

// ---------------- problem constants ----------------
#define kB   2
#define kN   16384
#define kDIM 512
#define kH   8
#define kD   64
#define kM   64
#define kSC  64
#define kROWS   (kB * kN)        // 32768
#define kCHUNKS 64               // encode split-N chunks (256 keys each)
#define kBH     (kB * kH)        // 16

// ---------------- scratch (device globals; no allocation allowed) ----------------
__device__ float g_xmid[kROWS * kDIM];            // (b*N+n, h*64+d)
__device__ float g_k[kBH * kN * kD];              // (b,h,n,d)
__device__ float g_v[kBH * kN * kD];
__device__ float g_q[kBH * kN * kD];
__device__ float g_mix[kROWS * kDIM];             // (b,n,h*64+d)
__device__ float g_kc[kBH * kSC * kD];
__device__ float g_vc[kBH * kSC * kD];
__device__ float g_psum[kCHUNKS * kBH * kM];
__device__ float g_pacc[kCHUNKS * kBH * kM * kD];
__device__ float g_latent[kBH * kM * kD];
// bf16 hi/lo split buffers for tensor-core GEMMs
__device__ __nv_bfloat16 g_ahi[kROWS * kDIM];     // 32 MB
__device__ __nv_bfloat16 g_alo[kROWS * kDIM];
__device__ __nv_bfloat16 g_whi[kDIM * kDIM];
__device__ __nv_bfloat16 g_wlo[kDIM * kDIM];

// ---------------- fp32 -> bf16 hi/lo split ----------------
__global__ __launch_bounds__(256) void conv_split(
    const float4* __restrict__ in, uint2* __restrict__ hi,
    uint2* __restrict__ lo, int n4) {
  int i = blockIdx.x * 256 + threadIdx.x;
  if (i >= n4) return;
  float4 v = in[i];
  __nv_bfloat16 h0 = __float2bfloat16(v.x), h1 = __float2bfloat16(v.y);
  __nv_bfloat16 h2 = __float2bfloat16(v.z), h3 = __float2bfloat16(v.w);
  __nv_bfloat16 l0 = __float2bfloat16(v.x - __bfloat162float(h0));
  __nv_bfloat16 l1 = __float2bfloat16(v.y - __bfloat162float(h1));
  __nv_bfloat16 l2 = __float2bfloat16(v.z - __bfloat162float(h2));
  __nv_bfloat16 l3 = __float2bfloat16(v.w - __bfloat162float(h3));
  uint2 ph, pl;
  ph.x = (uint32_t)__bfloat16_as_ushort(h0) | ((uint32_t)__bfloat16_as_ushort(h1) << 16);
  ph.y = (uint32_t)__bfloat16_as_ushort(h2) | ((uint32_t)__bfloat16_as_ushort(h3) << 16);
  pl.x = (uint32_t)__bfloat16_as_ushort(l0) | ((uint32_t)__bfloat16_as_ushort(l1) << 16);
  pl.y = (uint32_t)__bfloat16_as_ushort(l2) | ((uint32_t)__bfloat16_as_ushort(l3) << 16);
  hi[i] = ph;
  lo[i] = pl;
}

// ---------------- warp-MMA helper ----------------
__device__ __forceinline__ void mma_bf16(float* d, const uint32_t* a,
                                         const uint32_t* b) {
  asm volatile(
      "mma.sync.aligned.m16n8k16.row.col.f32.bf16.bf16.f32 "
      "{%0,%1,%2,%3}, {%4,%5,%6,%7}, {%8,%9}, {%0,%1,%2,%3};"
      : "+f"(d[0]), "+f"(d[1]), "+f"(d[2]), "+f"(d[3])
      : "r"(a[0]), "r"(a[1]), "r"(a[2]), "r"(a[3]), "r"(b[0]), "r"(b[1]));
}

// ---------------- 3xBF16 mma.sync GEMM: C = A(32768x512) @ W(512x512)^T + bias ----------------
// CTA tile 128x128, BK=32, 8 warps in 4x2 grid (warp tile 32x64).
// Smem stride 20 words/row -> conflict-free fragment LDS (g*20+tg distinct banks).
#define SA_STRIDE 20
__global__ __launch_bounds__(256) void mma512(
    const uint4* __restrict__ Ahi, const uint4* __restrict__ Alo,
    const uint4* __restrict__ Bhi, const uint4* __restrict__ Blo,
    const float* __restrict__ bias, float* __restrict__ C) {
  __shared__ uint32_t sA[2][128][SA_STRIDE];   // [hi/lo][row][k-pair]
  __shared__ uint32_t sB[2][128][SA_STRIDE];
  int tid = threadIdx.x, wid = tid >> 5, lane = tid & 31;
  int wr = wid >> 1, wc = wid & 1;             // warp row 0..3, warp col 0..1
  int g = lane >> 2, tg = lane & 3;
  size_t br = (size_t)blockIdx.y * 128;
  int bc = blockIdx.x * 128;

  float acc[2][8][4];
#pragma unroll
  for (int mt = 0; mt < 2; mt++)
#pragma unroll
    for (int nt = 0; nt < 8; nt++)
#pragma unroll
      for (int j = 0; j < 4; j++) acc[mt][nt][j] = 0.f;

  for (int kc = 0; kc < 16; kc++) {            // K chunks of 32
    __syncthreads();
#pragma unroll 2
    for (int idx = tid; idx < 512; idx += 256) {
      int r = idx >> 2, c4 = idx & 3;          // row, 8-elem group
      size_t ga = (br + r) * 64 + kc * 4 + c4; // uint4 index into bf16[.,512]
      size_t gb = ((size_t)bc + r) * 64 + kc * 4 + c4;
      uint4 ah = Ahi[ga], al = Alo[ga], bh = Bhi[gb], bl = Blo[gb];
      uint32_t* pa0 = &sA[0][r][c4 * 4];
      uint32_t* pa1 = &sA[1][r][c4 * 4];
      uint32_t* pb0 = &sB[0][r][c4 * 4];
      uint32_t* pb1 = &sB[1][r][c4 * 4];
      pa0[0] = ah.x; pa0[1] = ah.y; pa0[2] = ah.z; pa0[3] = ah.w;
      pa1[0] = al.x; pa1[1] = al.y; pa1[2] = al.z; pa1[3] = al.w;
      pb0[0] = bh.x; pb0[1] = bh.y; pb0[2] = bh.z; pb0[3] = bh.w;
      pb1[0] = bl.x; pb1[1] = bl.y; pb1[2] = bl.z; pb1[3] = bl.w;
    }
    __syncthreads();
#pragma unroll
    for (int ks = 0; ks < 2; ks++) {           // two k16 steps per chunk
      uint32_t af[2][2][4];                    // [hi/lo][mtile][frag]
#pragma unroll
      for (int h = 0; h < 2; h++)
#pragma unroll
        for (int mt = 0; mt < 2; mt++) {
          int row = wr * 32 + mt * 16;
          af[h][mt][0] = sA[h][row + g][ks * 8 + tg];
          af[h][mt][1] = sA[h][row + g + 8][ks * 8 + tg];
          af[h][mt][2] = sA[h][row + g][ks * 8 + tg + 4];
          af[h][mt][3] = sA[h][row + g + 8][ks * 8 + tg + 4];
        }
      uint32_t bfr[2][8][2];
#pragma unroll
      for (int h = 0; h < 2; h++)
#pragma unroll
        for (int nt = 0; nt < 8; nt++) {
          int col = wc * 64 + nt * 8;
          bfr[h][nt][0] = sB[h][col + g][ks * 8 + tg];
          bfr[h][nt][1] = sB[h][col + g][ks * 8 + tg + 4];
        }
#pragma unroll
      for (int mt = 0; mt < 2; mt++)
#pragma unroll
        for (int nt = 0; nt < 8; nt++) {
          mma_bf16(acc[mt][nt], af[0][mt], bfr[0][nt]);  // hi*hi
          mma_bf16(acc[mt][nt], af[0][mt], bfr[1][nt]);  // hi*lo
          mma_bf16(acc[mt][nt], af[1][mt], bfr[0][nt]);  // lo*hi
        }
    }
  }

  // epilogue: c-frag rows g, g+8; cols 2*tg, 2*tg+1 (contiguous -> float2)
#pragma unroll
  for (int mt = 0; mt < 2; mt++) {
    size_t row0 = br + wr * 32 + mt * 16 + g;
#pragma unroll
    for (int nt = 0; nt < 8; nt++) {
      int col = bc + wc * 64 + nt * 8 + tg * 2;
      float bx0 = bias[col], bx1 = bias[col + 1];
      float2* p0 = (float2*)&C[row0 * 512 + col];
      float2* p1 = (float2*)&C[(row0 + 8) * 512 + col];
      *p0 = make_float2(acc[mt][nt][0] + bx0, acc[mt][nt][1] + bx1);
      *p1 = make_float2(acc[mt][nt][2] + bx0, acc[mt][nt][3] + bx1);
    }
  }
}

// ---------------- K_ctx: kc/vc = context @ Wck^T/Wcv^T + bias ----------------
__global__ __launch_bounds__(256) void ctx_proj(
    const float* __restrict__ context, const float* __restrict__ Wck,
    const float* __restrict__ bck, const float* __restrict__ Wcv,
    const float* __restrict__ bcv) {
  __shared__ float sctx[kSC * kD];
  int tid = threadIdx.x, bh = blockIdx.x;
  for (int idx = tid; idx < kSC * kD; idx += 256)
    sctx[idx] = context[(size_t)bh * kSC * kD + idx];
  __syncthreads();
  for (int t = tid; t < 2 * kSC * kD; t += 256) {
    int sel = t >> 12;
    int r = t & 4095;
    int s = r >> 6, d = r & 63;
    const float* W = sel ? Wcv : Wck;
    float acc = sel ? bcv[d] : bck[d];
#pragma unroll 8
    for (int c = 0; c < 64; c++) acc += sctx[s * 64 + c] * W[d * 64 + c];
    (sel ? g_vc : g_kc)[(size_t)bh * 4096 + s * 64 + d] = acc;
  }
}

// ---------------- KVQ: per token, all heads: k|v|q head-projections ----------------
__global__ __launch_bounds__(256) void kvq_proj(
    const float* __restrict__ Wk, const float* __restrict__ bk,
    const float* __restrict__ Wv, const float* __restrict__ bv,
    const float* __restrict__ Wq, const float* __restrict__ bq) {
  __shared__ float sW[64 * 192];
  int tid = threadIdx.x;
  for (int idx = tid; idx < 64 * 192; idx += 256) {
    int i = idx / 192, col = idx % 192;
    float w;
    if (col < 64)       w = Wk[col * 64 + i];
    else if (col < 128) w = Wv[(col - 64) * 64 + i];
    else                w = Wq[(col - 128) * 64 + i];
    sW[idx] = w;
  }
  __syncthreads();
  int warp = tid >> 5, lane = tid & 31;
  int bn = blockIdx.x * 8 + warp;
  const float* xr = g_xmid + (size_t)bn * 512;
  float x0[8], x1[8];
#pragma unroll
  for (int h = 0; h < 8; h++) {
    x0[h] = xr[h * 64 + lane];
    x1[h] = xr[h * 64 + lane + 32];
  }
  float bias[6];
#pragma unroll
  for (int j = 0; j < 6; j++) {
    int col = lane + 32 * j;
    bias[j] = (col < 64) ? bk[col] : (col < 128) ? bv[col - 64] : bq[col - 128];
  }
  float acc[8][6];
#pragma unroll
  for (int h = 0; h < 8; h++)
#pragma unroll
    for (int j = 0; j < 6; j++) acc[h][j] = bias[j];

#pragma unroll 8
  for (int i = 0; i < 64; i++) {
    float wv[6];
#pragma unroll
    for (int j = 0; j < 6; j++) wv[j] = sW[i * 192 + lane + 32 * j];
#pragma unroll
    for (int h = 0; h < 8; h++) {
      float xv = __shfl_sync(0xffffffffu, (i < 32) ? x0[h] : x1[h], i & 31);
#pragma unroll
      for (int j = 0; j < 6; j++) acc[h][j] += xv * wv[j];
    }
  }
  int b = bn >> 14, n = bn & (kN - 1);
#pragma unroll
  for (int h = 0; h < 8; h++) {
    size_t dst = ((size_t)(b * kH + h) * kN + n) * 64;
    g_k[dst + lane]      = acc[h][0];
    g_k[dst + lane + 32] = acc[h][1];
    g_v[dst + lane]      = acc[h][2];
    g_v[dst + lane + 32] = acc[h][3];
    g_q[dst + lane]      = acc[h][4];
    g_q[dst + lane + 32] = acc[h][5];
  }
}

// ---------------- encode partial (vectorized LDS, conflict-free padding) ----------------
__global__ __launch_bounds__(256) void enc_partial(const float* __restrict__ qg) {
  __shared__ float sQ[64 * 68];
  __shared__ float sK[32 * 68];
  __shared__ float sV[32 * 72];
  __shared__ float sP[64 * 33];
  int tid = threadIdx.x;
  int c = blockIdx.x, bh = blockIdx.y;
  int h = bh & 7;
  for (int idx = tid; idx < 1024; idx += 256) {
    int m = idx >> 4, d4 = idx & 15;
    *(float4*)&sQ[m * 68 + d4 * 4] =
        *(const float4*)&qg[(h * 64 + m) * 64 + d4 * 4];
  }
  int m_t = tid >> 2, quad = tid & 3, d0 = quad * 16;
  float acc[16];
#pragma unroll
  for (int j = 0; j < 16; j++) acc[j] = 0.f;
  float lsum = 0.f;
  int base = bh * kN + c * 256;
  for (int nt = 0; nt < 8; nt++) {
    __syncthreads();
    for (int idx = tid; idx < 512; idx += 256) {
      int r = idx >> 4, d4 = idx & 15;
      size_t src = (size_t)(base + nt * 32 + r) * 64 + d4 * 4;
      *(float4*)&sK[r * 68 + d4 * 4] = *(const float4*)&g_k[src];
      *(float4*)&sV[r * 72 + d4 * 4] = *(const float4*)&g_v[src];
    }
    __syncthreads();
    float dot[8];
#pragma unroll
    for (int ii = 0; ii < 8; ii++) dot[ii] = 0.f;
#pragma unroll
    for (int i = 0; i < 64; i += 4) {
      float4 qv = *(const float4*)&sQ[m_t * 68 + i];
#pragma unroll
      for (int ii = 0; ii < 8; ii++) {
        float4 kv = *(const float4*)&sK[(quad * 8 + ii) * 68 + i];
        dot[ii] += qv.x * kv.x + qv.y * kv.y + qv.z * kv.z + qv.w * kv.w;
      }
    }
#pragma unroll
    for (int ii = 0; ii < 8; ii++) {
      float e = __expf(dot[ii]);
      sP[m_t * 33 + quad * 8 + ii] = e;
      lsum += e;
    }
    __syncthreads();
#pragma unroll 4
    for (int np = 0; np < 32; np++) {
      float p = sP[m_t * 33 + np];
      const float* vr = sV + np * 72 + d0;
      float4 v0 = *(const float4*)(vr + 0);
      float4 v1 = *(const float4*)(vr + 4);
      float4 v2 = *(const float4*)(vr + 8);
      float4 v3 = *(const float4*)(vr + 12);
      acc[0] += p * v0.x;  acc[1] += p * v0.y;  acc[2] += p * v0.z;  acc[3] += p * v0.w;
      acc[4] += p * v1.x;  acc[5] += p * v1.y;  acc[6] += p * v1.z;  acc[7] += p * v1.w;
      acc[8] += p * v2.x;  acc[9] += p * v2.y;  acc[10] += p * v2.z; acc[11] += p * v2.w;
      acc[12] += p * v3.x; acc[13] += p * v3.y; acc[14] += p * v3.z; acc[15] += p * v3.w;
    }
  }
  lsum += __shfl_xor_sync(0xffffffffu, lsum, 1);
  lsum += __shfl_xor_sync(0xffffffffu, lsum, 2);
  size_t ob = (size_t)(c * kBH + bh) * 64 + m_t;
  if (quad == 0) g_psum[ob] = lsum;
#pragma unroll
  for (int j = 0; j < 16; j++) g_pacc[ob * 64 + d0 + j] = acc[j];
}

// ---------------- encode reduce ----------------
__global__ __launch_bounds__(256) void enc_reduce() {
  __shared__ float sinv[64];
  int tid = threadIdx.x, bh = blockIdx.x;
  if (tid < 64) {
    float s = 0.f;
    for (int c = 0; c < kCHUNKS; c++)
      s += g_psum[(size_t)(c * kBH + bh) * 64 + tid];
    sinv[tid] = 1.f / s;
  }
  __syncthreads();
  for (int idx = tid; idx < 4096; idx += 256) {
    int m = idx >> 6, d = idx & 63;
    float s = 0.f;
    for (int c = 0; c < kCHUNKS; c++)
      s += g_pacc[((size_t)(c * kBH + bh) * 64 + m) * 64 + d];
    g_latent[(size_t)bh * 4096 + m * 64 + d] = s * sinv[m];
  }
}

// ---------------- decode (self path) ----------------
__global__ __launch_bounds__(256) void dec_self(const float* __restrict__ qg) {
  __shared__ float sQg[64 * 65];
  __shared__ float sLat[64 * 65];
  int tid = threadIdx.x;
  int bh = blockIdx.y, h = bh & 7, b = bh >> 3;
  for (int idx = tid; idx < 4096; idx += 256) {
    int m = idx >> 6, d = idx & 63;
    sQg[m * 65 + d] = qg[(h * 64 + m) * 64 + d];
    sLat[m * 65 + d] = g_latent[(size_t)bh * 4096 + idx];
  }
  __syncthreads();
  int warp = tid >> 5, lane = tid & 31;
  int n0 = blockIdx.x * 64 + warp * 8;
  for (int r = 0; r < 8; r++) {
    int n = n0 + r;
    const float* kp = g_k + ((size_t)bh * kN + n) * 64;
    float k0 = kp[lane], k1 = kp[lane + 32];
    float s0 = 0.f, s1 = 0.f;
#pragma unroll 8
    for (int d = 0; d < 64; d++) {
      float kv = __shfl_sync(0xffffffffu, (d < 32) ? k0 : k1, d & 31);
      s0 += kv * sQg[lane * 65 + d];
      s1 += kv * sQg[(lane + 32) * 65 + d];
    }
    float e0 = __expf(s0), e1 = __expf(s1);
    float sum = e0 + e1;
#pragma unroll
    for (int o = 16; o > 0; o >>= 1) sum += __shfl_xor_sync(0xffffffffu, sum, o);
    float inv = 1.f / sum;
    float t0 = 0.f, t1 = 0.f;
#pragma unroll 8
    for (int m = 0; m < 64; m++) {
      float ev = __shfl_sync(0xffffffffu, (m < 32) ? e0 : e1, m & 31);
      t0 += ev * sLat[m * 65 + lane];
      t1 += ev * sLat[m * 65 + lane + 32];
    }
    float* op = g_mix + ((size_t)b * kN + n) * 512 + h * 64;
    op[lane] = t0 * inv;
    op[lane + 32] = t1 * inv;
  }
}

// ---------------- cross path + sigmoid gate ----------------
__global__ __launch_bounds__(256) void dec_cross(const float* __restrict__ smix) {
  __shared__ float sKc[64 * 65];
  __shared__ float sVc[64 * 65];
  int tid = threadIdx.x;
  int bh = blockIdx.y, h = bh & 7, b = bh >> 3;
  for (int idx = tid; idx < 4096; idx += 256) {
    int s = idx >> 6, d = idx & 63;
    sKc[s * 65 + d] = g_kc[(size_t)bh * 4096 + idx];
    sVc[s * 65 + d] = g_vc[(size_t)bh * 4096 + idx];
  }
  __syncthreads();
  float wmix = 1.f / (1.f + __expf(-smix[0]));
  int warp = tid >> 5, lane = tid & 31;
  int n0 = blockIdx.x * 64 + warp * 8;
  for (int r = 0; r < 8; r++) {
    int n = n0 + r;
    const float* qp = g_q + ((size_t)bh * kN + n) * 64;
    float q0 = qp[lane], q1 = qp[lane + 32];
    float s0 = 0.f, s1 = 0.f;
#pragma unroll 8
    for (int d = 0; d < 64; d++) {
      float qv = __shfl_sync(0xffffffffu, (d < 32) ? q0 : q1, d & 31);
      s0 += qv * sKc[lane * 65 + d];
      s1 += qv * sKc[(lane + 32) * 65 + d];
    }
    float e0 = __expf(s0), e1 = __expf(s1);
    float sum = e0 + e1;
#pragma unroll
    for (int o = 16; o > 0; o >>= 1) sum += __shfl_xor_sync(0xffffffffu, sum, o);
    float inv = 1.f / sum;
    float t0 = 0.f, t1 = 0.f;
#pragma unroll 8
    for (int s = 0; s < 64; s++) {
      float ev = __shfl_sync(0xffffffffu, (s < 32) ? e0 : e1, s & 31);
      t0 += ev * sVc[s * 65 + lane];
      t1 += ev * sVc[s * 65 + lane + 32];
    }
    float* op = g_mix + ((size_t)b * kN + n) * 512 + h * 64;
    op[lane]      = wmix * op[lane]      + (1.f - wmix) * t0 * inv;
    op[lane + 32] = wmix * op[lane + 32] + (1.f - wmix) * t1 * inv;
  }
}

// ---------------- launch ----------------
extern "C" void kernel_launch(void* const* d_in, const int* in_sizes, int n_in,
                              void* d_out, int out_size) {
  const float* x    = (const float*)d_in[0];
  const float* ctx  = (const float*)d_in[1];
  const float* qg   = (const float*)d_in[2];
  const float* Wx   = (const float*)d_in[3];
  const float* bx   = (const float*)d_in[4];
  const float* Wk   = (const float*)d_in[5];
  const float* bk   = (const float*)d_in[6];
  const float* Wv   = (const float*)d_in[7];
  const float* bv   = (const float*)d_in[8];
  const float* Wcq  = (const float*)d_in[9];
  const float* bcq  = (const float*)d_in[10];
  const float* Wck  = (const float*)d_in[11];
  const float* bck  = (const float*)d_in[12];
  const float* Wcv  = (const float*)d_in[13];
  const float* bcv  = (const float*)d_in[14];
  const float* smx  = (const float*)d_in[15];
  const float* Wo   = (const float*)d_in[16];
  const float* bo   = (const float*)d_in[17];
  float* out = (float*)d_out;

  void *xmid_p = nullptr, *mix_p = nullptr;
  void *ahi_p = nullptr, *alo_p = nullptr, *whi_p = nullptr, *wlo_p = nullptr;
  cudaGetSymbolAddress(&xmid_p, g_xmid);
  cudaGetSymbolAddress(&mix_p, g_mix);
  cudaGetSymbolAddress(&ahi_p, g_ahi);
  cudaGetSymbolAddress(&alo_p, g_alo);
  cudaGetSymbolAddress(&whi_p, g_whi);
  cudaGetSymbolAddress(&wlo_p, g_wlo);

  const int nA4 = kROWS * kDIM / 4;   // 4194304
  const int nW4 = kDIM * kDIM / 4;    // 65536

  ctx_proj<<<kBH, 256>>>(ctx, Wck, bck, Wcv, bcv);
  // --- projection 1: xmid = x @ Wx^T + bx (3x-bf16 tensor path) ---
  conv_split<<<nA4 / 256, 256>>>((const float4*)x, (uint2*)ahi_p, (uint2*)alo_p, nA4);
  conv_split<<<nW4 / 256, 256>>>((const float4*)Wx, (uint2*)whi_p, (uint2*)wlo_p, nW4);
  mma512<<<dim3(4, kROWS / 128), 256>>>(
      (const uint4*)ahi_p, (const uint4*)alo_p,
      (const uint4*)whi_p, (const uint4*)wlo_p, bx, (float*)xmid_p);

  kvq_proj<<<kROWS / 8, 256>>>(Wk, bk, Wv, bv, Wcq, bcq);
  enc_partial<<<dim3(kCHUNKS, kBH), 256>>>(qg);
  enc_reduce<<<kBH, 256>>>();
  dec_self<<<dim3(kN / 64, kBH), 256>>>(qg);
  dec_cross<<<dim3(kN / 64, kBH), 256>>>(smx);

  // --- projection 2: out = mix @ Wo^T + bo ---
  conv_split<<<nA4 / 256, 256>>>((const float4*)mix_p, (uint2*)ahi_p, (uint2*)alo_p, nA4);
  conv_split<<<nW4 / 256, 256>>>((const float4*)Wo, (uint2*)whi_p, (uint2*)wlo_p, nW4);
  mma512<<<dim3(4, kROWS / 128), 256>>>(
      (const uint4*)ahi_p, (const uint4*)alo_p,
      (const uint4*)whi_p, (const uint4*)wlo_p, bo, out);
}

// round 5
// speedup vs baseline: 2.2334x; 2.0835x over previous
#include <cuda_runtime.h>
#include <cuda_bf16.h>
#include <cstdint>

// ---------------- problem constants ----------------
#define kB   2
#define kN   16384
#define kDIM 512
#define kH   8
#define kROWS (kB * kN)          // 32768
#define kBH   (kB * kH)          // 16
#define kSLOTS 256               // enc partial slots (128 chunks x 2 warp-halves)

// ---------------- scratch (device globals) ----------------
__device__ ushort g_xh[kROWS * kDIM],  g_xl[kROWS * kDIM];      // xmid hi/lo
__device__ ushort g_mixh[kROWS * kDIM], g_mixl[kROWS * kDIM];   // gated mix hi/lo
__device__ ushort g_kh[kBH * kN * 64], g_kl[kBH * kN * 64];
__device__ ushort g_qh[kBH * kN * 64], g_ql[kBH * kN * 64];
__device__ ushort g_vth[kBH * 64 * kN], g_vtl[kBH * 64 * kN];   // v transposed [bh][d][n]
__device__ ushort g_qgh[512 * 64], g_qgl[512 * 64];             // [h*64+m][d]
__device__ ushort g_kch[kBH * 4096], g_kcl[kBH * 4096];         // [bh][s][d]
__device__ ushort g_vcth[kBH * 4096], g_vctl[kBH * 4096];       // [bh][d][s]
__device__ ushort g_lath[kBH * 4096], g_latl[kBH * 4096];       // latent^T [bh][d][m]
__device__ ushort g_wkvqh[192 * 64], g_wkvql[192 * 64];         // [col(k|v|q)][din]
__device__ ushort g_ahi[kROWS * kDIM], g_alo[kROWS * kDIM];     // proj A split (x)
__device__ ushort g_whi[kDIM * kDIM], g_wlo[kDIM * kDIM];       // proj W split
__device__ float  g_psum[kSLOTS * kBH * 64];
__device__ float  g_pacc[(size_t)kSLOTS * kBH * 4096];          // 67 MB

// ---------------- helpers ----------------
__device__ __forceinline__ ushort bfhi(float x) {
  return __bfloat16_as_ushort(__float2bfloat16(x));
}
__device__ __forceinline__ float bfval(ushort u) {
  return __bfloat162float(__ushort_as_bfloat16(u));
}
__device__ __forceinline__ void split2(float a, float b, uint32_t& hi, uint32_t& lo) {
  ushort ha = bfhi(a), hb = bfhi(b);
  hi = (uint32_t)ha | ((uint32_t)hb << 16);
  lo = (uint32_t)bfhi(a - bfval(ha)) | ((uint32_t)bfhi(b - bfval(hb)) << 16);
}
__device__ __forceinline__ void mma_bf16(float* d, const uint32_t* a,
                                         const uint32_t* b) {
  asm volatile(
      "mma.sync.aligned.m16n8k16.row.col.f32.bf16.bf16.f32 "
      "{%0,%1,%2,%3}, {%4,%5,%6,%7}, {%8,%9}, {%0,%1,%2,%3};"
      : "+f"(d[0]), "+f"(d[1]), "+f"(d[2]), "+f"(d[3])
      : "r"(a[0]), "r"(a[1]), "r"(a[2]), "r"(a[3]), "r"(b[0]), "r"(b[1]));
}
// load R rows x (w32 uint32) bf16 tile from gmem into smem with row stride sstr
__device__ __forceinline__ void load_tile(uint32_t* s, const ushort* gp, int rows,
                                          int w32, size_t gstr, int sstr, int tid) {
  int w4 = w32 >> 2;
  for (int idx = tid; idx < rows * w4; idx += 256) {
    int r = idx / w4, w = idx % w4;
    uint4 v = *(const uint4*)(gp + (size_t)r * gstr + w * 8);
    uint32_t* p = s + r * sstr + w * 4;
    p[0] = v.x; p[1] = v.y; p[2] = v.z; p[3] = v.w;
  }
}
__device__ __forceinline__ void lda_f(uint32_t* af, const uint32_t* s, int row,
                                      int ks, int g, int tg, int str) {
  af[0] = s[(row + g) * str + ks * 8 + tg];
  af[1] = s[(row + g + 8) * str + ks * 8 + tg];
  af[2] = s[(row + g) * str + ks * 8 + tg + 4];
  af[3] = s[(row + g + 8) * str + ks * 8 + tg + 4];
}
__device__ __forceinline__ void ldb_f(uint32_t* bf, const uint32_t* s, int col,
                                      int koff, int g, int tg, int str) {
  bf[0] = s[(col + g) * str + koff + tg];
  bf[1] = s[(col + g) * str + koff + tg + 4];
}

// stage1: acc[nt] += Atile(rows arow..arow+15) x Btile(cols bcol+nt*8), 3-term split
__device__ __forceinline__ void attn_logits(const uint32_t* sAh, const uint32_t* sAl,
                                            int arow, const uint32_t* sBh,
                                            const uint32_t* sBl, int bcol,
                                            float acc[8][4], int g, int tg) {
#pragma unroll
  for (int nt = 0; nt < 8; nt++)
#pragma unroll
    for (int j = 0; j < 4; j++) acc[nt][j] = 0.f;
#pragma unroll
  for (int ks = 0; ks < 4; ks++) {
    uint32_t ah[4], al[4];
    lda_f(ah, sAh, arow, ks, g, tg, 36);
    lda_f(al, sAl, arow, ks, g, tg, 36);
#pragma unroll
    for (int nt = 0; nt < 8; nt++) {
      uint32_t bh2[2], bl2[2];
      ldb_f(bh2, sBh, bcol + nt * 8, ks * 8, g, tg, 36);
      ldb_f(bl2, sBl, bcol + nt * 8, ks * 8, g, tg, 36);
      mma_bf16(acc[nt], ah, bh2);
      mma_bf16(acc[nt], ah, bl2);
      mma_bf16(acc[nt], al, bh2);
    }
  }
}
// pack exp'd probabilities (C frags) into A frags (hi/lo)
__device__ __forceinline__ void pack_p(const float p[8][4], uint32_t pah[4][4],
                                       uint32_t pal[4][4]) {
#pragma unroll
  for (int j = 0; j < 4; j++) {
    split2(p[2 * j][0], p[2 * j][1], pah[j][0], pal[j][0]);
    split2(p[2 * j][2], p[2 * j][3], pah[j][1], pal[j][1]);
    split2(p[2 * j + 1][0], p[2 * j + 1][1], pah[j][2], pal[j][2]);
    split2(p[2 * j + 1][2], p[2 * j + 1][3], pah[j][3], pal[j][3]);
  }
}
// stage2: acc[nt] = P(m16 x k64) x B(cols nt*8, k offset koff), 3-term
__device__ __forceinline__ void attn_pv(const uint32_t pah[4][4],
                                        const uint32_t pal[4][4],
                                        const uint32_t* sBh, const uint32_t* sBl,
                                        int bstr, int koff, float acc[8][4],
                                        int g, int tg) {
#pragma unroll
  for (int nt = 0; nt < 8; nt++)
#pragma unroll
    for (int j = 0; j < 4; j++) acc[nt][j] = 0.f;
#pragma unroll
  for (int ks = 0; ks < 4; ks++) {
#pragma unroll
    for (int nt = 0; nt < 8; nt++) {
      uint32_t bh2[2], bl2[2];
      bh2[0] = sBh[(nt * 8 + g) * bstr + koff + ks * 8 + tg];
      bh2[1] = sBh[(nt * 8 + g) * bstr + koff + ks * 8 + tg + 4];
      bl2[0] = sBl[(nt * 8 + g) * bstr + koff + ks * 8 + tg];
      bl2[1] = sBl[(nt * 8 + g) * bstr + koff + ks * 8 + tg + 4];
      mma_bf16(acc[nt], pah[ks], bh2);
      mma_bf16(acc[nt], pah[ks], bl2);
      mma_bf16(acc[nt], pal[ks], bh2);
    }
  }
}

// ---------------- fp32 -> bf16 hi/lo split (elementwise) ----------------
__global__ __launch_bounds__(256) void conv_split(
    const float4* __restrict__ in, uint2* __restrict__ hi,
    uint2* __restrict__ lo, int n4) {
  int i = blockIdx.x * 256 + threadIdx.x;
  if (i >= n4) return;
  float4 v = in[i];
  uint32_t h0, l0, h1, l1;
  split2(v.x, v.y, h0, l0);
  split2(v.z, v.w, h1, l1);
  hi[i] = make_uint2(h0, h1);
  lo[i] = make_uint2(l0, l1);
}

// ---------------- prep: stacked kvq weights [192][64] hi/lo ----------------
__global__ __launch_bounds__(256) void prep_wkvq(const float* __restrict__ Wk,
                                                 const float* __restrict__ Wv,
                                                 const float* __restrict__ Wq) {
  int i = blockIdx.x * 256 + threadIdx.x;
  if (i >= 192 * 64) return;
  int r = i >> 6, cin = i & 63;
  float w = (r < 64) ? Wk[r * 64 + cin]
            : (r < 128) ? Wv[(r - 64) * 64 + cin] : Wq[(r - 128) * 64 + cin];
  ushort h = bfhi(w);
  g_wkvqh[i] = h;
  g_wkvql[i] = bfhi(w - bfval(h));
}

// ---------------- ctx: kc [bh][s][d], vcT [bh][d][s] hi/lo ----------------
__global__ __launch_bounds__(256) void ctx_proj(
    const float* __restrict__ context, const float* __restrict__ Wck,
    const float* __restrict__ bck, const float* __restrict__ Wcv,
    const float* __restrict__ bcv) {
  __shared__ float sctx[64 * 64];
  int tid = threadIdx.x, bh = blockIdx.x;
  for (int idx = tid; idx < 4096; idx += 256)
    sctx[idx] = context[(size_t)bh * 4096 + idx];
  __syncthreads();
  for (int t = tid; t < 8192; t += 256) {
    int sel = t >> 12;
    int r = t & 4095;
    int s = r >> 6, d = r & 63;
    const float* W = sel ? Wcv : Wck;
    float acc = sel ? bcv[d] : bck[d];
#pragma unroll 8
    for (int c = 0; c < 64; c++) acc += sctx[s * 64 + c] * W[d * 64 + c];
    ushort h = bfhi(acc), l = bfhi(acc - bfval(h));
    if (sel == 0) {
      g_kch[bh * 4096 + s * 64 + d] = h;
      g_kcl[bh * 4096 + s * 64 + d] = l;
    } else {
      g_vcth[bh * 4096 + d * 64 + s] = h;
      g_vctl[bh * 4096 + d * 64 + s] = l;
    }
  }
}

// ---------------- proj GEMM: C = A(32768x512) @ W(512x512)^T + bias ----------------
// SPLITOUT=0: f32 C; SPLITOUT=1: hi/lo ushort outputs.
#define SA_STRIDE 20
template <int SPLITOUT>
__global__ __launch_bounds__(256) void mma512(
    const uint4* __restrict__ Ahi, const uint4* __restrict__ Alo,
    const uint4* __restrict__ Bhi, const uint4* __restrict__ Blo,
    const float* __restrict__ bias, float* __restrict__ C,
    ushort* __restrict__ Ch, ushort* __restrict__ Cl) {
  __shared__ uint32_t sA[2][128][SA_STRIDE];
  __shared__ uint32_t sB[2][128][SA_STRIDE];
  int tid = threadIdx.x, wid = tid >> 5, lane = tid & 31;
  int wr = wid >> 1, wc = wid & 1;
  int g = lane >> 2, tg = lane & 3;
  size_t br = (size_t)blockIdx.y * 128;
  int bc = blockIdx.x * 128;

  float acc[2][8][4];
#pragma unroll
  for (int mt = 0; mt < 2; mt++)
#pragma unroll
    for (int nt = 0; nt < 8; nt++)
#pragma unroll
      for (int j = 0; j < 4; j++) acc[mt][nt][j] = 0.f;

  uint4 pre[2][4];
#pragma unroll
  for (int i = 0; i < 2; i++) {
    int idx = tid + i * 256;
    int r = idx >> 2, c4 = idx & 3;
    size_t ga = (br + r) * 64 + c4;
    size_t gb = ((size_t)bc + r) * 64 + c4;
    pre[i][0] = Ahi[ga]; pre[i][1] = Alo[ga];
    pre[i][2] = Bhi[gb]; pre[i][3] = Blo[gb];
  }

  for (int kc = 0; kc < 16; kc++) {
    __syncthreads();
#pragma unroll
    for (int i = 0; i < 2; i++) {
      int idx = tid + i * 256;
      int r = idx >> 2, c4 = idx & 3;
      uint32_t* pa0 = &sA[0][r][c4 * 4];
      uint32_t* pa1 = &sA[1][r][c4 * 4];
      uint32_t* pb0 = &sB[0][r][c4 * 4];
      uint32_t* pb1 = &sB[1][r][c4 * 4];
      pa0[0] = pre[i][0].x; pa0[1] = pre[i][0].y; pa0[2] = pre[i][0].z; pa0[3] = pre[i][0].w;
      pa1[0] = pre[i][1].x; pa1[1] = pre[i][1].y; pa1[2] = pre[i][1].z; pa1[3] = pre[i][1].w;
      pb0[0] = pre[i][2].x; pb0[1] = pre[i][2].y; pb0[2] = pre[i][2].z; pb0[3] = pre[i][2].w;
      pb1[0] = pre[i][3].x; pb1[1] = pre[i][3].y; pb1[2] = pre[i][3].z; pb1[3] = pre[i][3].w;
    }
    __syncthreads();
    if (kc < 15) {
#pragma unroll
      for (int i = 0; i < 2; i++) {
        int idx = tid + i * 256;
        int r = idx >> 2, c4 = idx & 3;
        size_t ga = (br + r) * 64 + (kc + 1) * 4 + c4;
        size_t gb = ((size_t)bc + r) * 64 + (kc + 1) * 4 + c4;
        pre[i][0] = Ahi[ga]; pre[i][1] = Alo[ga];
        pre[i][2] = Bhi[gb]; pre[i][3] = Blo[gb];
      }
    }
#pragma unroll
    for (int ks = 0; ks < 2; ks++) {
      uint32_t af[2][2][4];
#pragma unroll
      for (int h = 0; h < 2; h++)
#pragma unroll
        for (int mt = 0; mt < 2; mt++) {
          int row = wr * 32 + mt * 16;
          af[h][mt][0] = sA[h][row + g][ks * 8 + tg];
          af[h][mt][1] = sA[h][row + g + 8][ks * 8 + tg];
          af[h][mt][2] = sA[h][row + g][ks * 8 + tg + 4];
          af[h][mt][3] = sA[h][row + g + 8][ks * 8 + tg + 4];
        }
      uint32_t bfr[2][8][2];
#pragma unroll
      for (int h = 0; h < 2; h++)
#pragma unroll
        for (int nt = 0; nt < 8; nt++) {
          int col = wc * 64 + nt * 8;
          bfr[h][nt][0] = sB[h][col + g][ks * 8 + tg];
          bfr[h][nt][1] = sB[h][col + g][ks * 8 + tg + 4];
        }
#pragma unroll
      for (int mt = 0; mt < 2; mt++)
#pragma unroll
        for (int nt = 0; nt < 8; nt++) {
          mma_bf16(acc[mt][nt], af[0][mt], bfr[0][nt]);
          mma_bf16(acc[mt][nt], af[0][mt], bfr[1][nt]);
          mma_bf16(acc[mt][nt], af[1][mt], bfr[0][nt]);
        }
    }
  }

#pragma unroll
  for (int mt = 0; mt < 2; mt++) {
    size_t row0 = br + wr * 32 + mt * 16 + g;
#pragma unroll
    for (int nt = 0; nt < 8; nt++) {
      int col = bc + wc * 64 + nt * 8 + tg * 2;
      float bx0 = bias[col], bx1 = bias[col + 1];
      float v0 = acc[mt][nt][0] + bx0, v1 = acc[mt][nt][1] + bx1;
      float v2 = acc[mt][nt][2] + bx0, v3 = acc[mt][nt][3] + bx1;
      if (SPLITOUT) {
        uint32_t hi, lo;
        split2(v0, v1, hi, lo);
        *(uint32_t*)(Ch + row0 * 512 + col) = hi;
        *(uint32_t*)(Cl + row0 * 512 + col) = lo;
        split2(v2, v3, hi, lo);
        *(uint32_t*)(Ch + (row0 + 8) * 512 + col) = hi;
        *(uint32_t*)(Cl + (row0 + 8) * 512 + col) = lo;
      } else {
        *(float2*)&C[row0 * 512 + col] = make_float2(v0, v1);
        *(float2*)&C[(row0 + 8) * 512 + col] = make_float2(v2, v3);
      }
    }
  }
}

// ---------------- kvq: per (bh) K/V/Q = Xh @ Wkvq^T + bias ----------------
#define KA_H 0
#define KA_L 4608
#define KW_H 9216
#define KW_L 16128
#define KVQ_SMEM (23040 * 4)
__global__ __launch_bounds__(256) void kvq_mma(const float* __restrict__ bk,
                                               const float* __restrict__ bv,
                                               const float* __restrict__ bq) {
  extern __shared__ uint32_t sm[];
  int tid = threadIdx.x, wid = tid >> 5, lane = tid & 31;
  int g = lane >> 2, tg = lane & 3;
  int wr = wid >> 1, wc = wid & 1;
  int c = blockIdx.x, bh = blockIdx.y, h = bh & 7, b = bh >> 3;
  size_t abase = ((size_t)(b * kN + c * 128)) * 512 + h * 64;
  load_tile(sm + KA_H, g_xh + abase, 128, 32, 512, 36, tid);
  load_tile(sm + KA_L, g_xl + abase, 128, 32, 512, 36, tid);
  load_tile(sm + KW_H, g_wkvqh, 192, 32, 64, 36, tid);
  load_tile(sm + KW_L, g_wkvql, 192, 32, 64, 36, tid);
  __syncthreads();

  float acc[2][12][4];
#pragma unroll
  for (int mt = 0; mt < 2; mt++)
#pragma unroll
    for (int nt = 0; nt < 12; nt++)
#pragma unroll
      for (int j = 0; j < 4; j++) acc[mt][nt][j] = 0.f;

#pragma unroll
  for (int ks = 0; ks < 4; ks++) {
    uint32_t ah[2][4], al[2][4];
#pragma unroll
    for (int mt = 0; mt < 2; mt++) {
      lda_f(ah[mt], sm + KA_H, wr * 32 + mt * 16, ks, g, tg, 36);
      lda_f(al[mt], sm + KA_L, wr * 32 + mt * 16, ks, g, tg, 36);
    }
#pragma unroll
    for (int nt = 0; nt < 12; nt++) {
      uint32_t bh2[2], bl2[2];
      ldb_f(bh2, sm + KW_H, wc * 96 + nt * 8, ks * 8, g, tg, 36);
      ldb_f(bl2, sm + KW_L, wc * 96 + nt * 8, ks * 8, g, tg, 36);
#pragma unroll
      for (int mt = 0; mt < 2; mt++) {
        mma_bf16(acc[mt][nt], ah[mt], bh2);
        mma_bf16(acc[mt][nt], ah[mt], bl2);
        mma_bf16(acc[mt][nt], al[mt], bh2);
      }
    }
  }

#pragma unroll
  for (int mt = 0; mt < 2; mt++) {
    int tok = c * 128 + wr * 32 + mt * 16 + g;
#pragma unroll
    for (int nt = 0; nt < 12; nt++) {
      int col = wc * 96 + nt * 8 + tg * 2;
      int sel = col >> 6, d = col & 63;
      float b0 = (sel == 0) ? bk[d] : (sel == 1) ? bv[d] : bq[d];
      float b1 = (sel == 0) ? bk[d + 1] : (sel == 1) ? bv[d + 1] : bq[d + 1];
      float v0 = acc[mt][nt][0] + b0, v1 = acc[mt][nt][1] + b1;
      float v2 = acc[mt][nt][2] + b0, v3 = acc[mt][nt][3] + b1;
      if (sel == 1) {
        size_t vb = ((size_t)bh * 64 + d) * kN + tok;
        ushort hh;
        hh = bfhi(v0); g_vth[vb] = hh;          g_vtl[vb] = bfhi(v0 - bfval(hh));
        hh = bfhi(v2); g_vth[vb + 8] = hh;      g_vtl[vb + 8] = bfhi(v2 - bfval(hh));
        hh = bfhi(v1); g_vth[vb + kN] = hh;     g_vtl[vb + kN] = bfhi(v1 - bfval(hh));
        hh = bfhi(v3); g_vth[vb + kN + 8] = hh; g_vtl[vb + kN + 8] = bfhi(v3 - bfval(hh));
      } else {
        ushort* oh = (sel == 0) ? g_kh : g_qh;
        ushort* ol = (sel == 0) ? g_kl : g_ql;
        size_t ob = ((size_t)bh * kN + tok) * 64 + d;
        uint32_t hi, lo;
        split2(v0, v1, hi, lo);
        *(uint32_t*)(oh + ob) = hi; *(uint32_t*)(ol + ob) = lo;
        split2(v2, v3, hi, lo);
        *(uint32_t*)(oh + ob + 8 * 64) = hi; *(uint32_t*)(ol + ob + 8 * 64) = lo;
      }
    }
  }
}

// ---------------- encode: partial exp-sums + exp@V per chunk ----------------
#define EKH 0
#define EKL 4608
#define EQH 9216
#define EQL 11520
#define EVH 13824
#define EVL 18176
#define ENC_SMEM (22528 * 4)
__global__ __launch_bounds__(256) void enc_mma() {
  extern __shared__ uint32_t sm[];
  int tid = threadIdx.x, wid = tid >> 5, lane = tid & 31;
  int g = lane >> 2, tg = lane & 3;
  int wr = wid >> 1, wc = wid & 1;
  int c = blockIdx.x, bh = blockIdx.y, h = bh & 7;
  load_tile(sm + EQH, g_qgh + h * 4096, 64, 32, 64, 36, tid);
  load_tile(sm + EQL, g_qgl + h * 4096, 64, 32, 64, 36, tid);
  size_t tokbase = ((size_t)bh * kN + c * 128) * 64;
  load_tile(sm + EKH, g_kh + tokbase, 128, 32, 64, 36, tid);
  load_tile(sm + EKL, g_kl + tokbase, 128, 32, 64, 36, tid);
  size_t vtbase = (size_t)bh * 64 * kN + c * 128;
  load_tile(sm + EVH, g_vth + vtbase, 64, 64, kN, 68, tid);
  load_tile(sm + EVL, g_vtl + vtbase, 64, 64, kN, 68, tid);
  __syncthreads();

  float acc[8][4];
  attn_logits(sm + EQH, sm + EQL, wr * 16, sm + EKH, sm + EKL, wc * 64, acc, g, tg);
  float s0 = 0.f, s1 = 0.f;
#pragma unroll
  for (int nt = 0; nt < 8; nt++) {
    acc[nt][0] = __expf(acc[nt][0]); acc[nt][1] = __expf(acc[nt][1]);
    acc[nt][2] = __expf(acc[nt][2]); acc[nt][3] = __expf(acc[nt][3]);
    s0 += acc[nt][0] + acc[nt][1];
    s1 += acc[nt][2] + acc[nt][3];
  }
  s0 += __shfl_xor_sync(0xffffffffu, s0, 1);
  s0 += __shfl_xor_sync(0xffffffffu, s0, 2);
  s1 += __shfl_xor_sync(0xffffffffu, s1, 1);
  s1 += __shfl_xor_sync(0xffffffffu, s1, 2);
  int slot = c * 2 + wc;
  if (tg == 0) {
    size_t pb = ((size_t)slot * kBH + bh) * 64 + wr * 16 + g;
    g_psum[pb] = s0;
    g_psum[pb + 8] = s1;
  }
  uint32_t pah[4][4], pal[4][4];
  pack_p(acc, pah, pal);
  attn_pv(pah, pal, sm + EVH, sm + EVL, 68, wc * 32, acc, g, tg);
  size_t ab = ((size_t)slot * kBH + bh) * 4096 + (wr * 16 + g) * 64;
#pragma unroll
  for (int nt = 0; nt < 8; nt++) {
    int d = nt * 8 + tg * 2;
    *(float2*)&g_pacc[ab + d] = make_float2(acc[nt][0], acc[nt][1]);
    *(float2*)&g_pacc[ab + 8 * 64 + d] = make_float2(acc[nt][2], acc[nt][3]);
  }
}

// ---------------- encode reduce -> latent^T hi/lo ----------------
__global__ __launch_bounds__(256) void enc_reduce2() {
  __shared__ float sinv[64];
  int tid = threadIdx.x;
  int dchunk = blockIdx.x, bh = blockIdx.y;
  if (tid < 64) {
    float s = 0.f;
    for (int s2 = 0; s2 < kSLOTS; s2++)
      s += g_psum[((size_t)s2 * kBH + bh) * 64 + tid];
    sinv[tid] = 1.f / s;
  }
  __syncthreads();
  for (int idx = tid; idx < 512; idx += 256) {
    int e = dchunk * 512 + idx;
    int m = e >> 6, d = e & 63;
    float a = 0.f;
    for (int s2 = 0; s2 < kSLOTS; s2++)
      a += g_pacc[((size_t)s2 * kBH + bh) * 4096 + e];
    float v = a * sinv[m];
    ushort hh = bfhi(v);
    g_lath[bh * 4096 + d * 64 + m] = hh;
    g_latl[bh * 4096 + d * 64 + m] = bfhi(v - bfval(hh));
  }
}

// ---------------- fused decode-self + cross + gate -> mix hi/lo ----------------
#define TOKH 0
#define TOKL 4608
#define SQGH 9216
#define SQGL 11520
#define SKCH 13824
#define SKCL 16128
#define SLATH 18432
#define SLATL 20736
#define SVCH 23040
#define SVCL 25344
#define DEC_SMEM (27648 * 4)
__global__ __launch_bounds__(256) void dec_fused(const float* __restrict__ smx) {
  extern __shared__ uint32_t sm[];
  int tid = threadIdx.x, wid = tid >> 5, lane = tid & 31;
  int g = lane >> 2, tg = lane & 3;
  int c = blockIdx.x, bh = blockIdx.y, h = bh & 7, b = bh >> 3;
  load_tile(sm + SQGH, g_qgh + h * 4096, 64, 32, 64, 36, tid);
  load_tile(sm + SQGL, g_qgl + h * 4096, 64, 32, 64, 36, tid);
  load_tile(sm + SKCH, g_kch + bh * 4096, 64, 32, 64, 36, tid);
  load_tile(sm + SKCL, g_kcl + bh * 4096, 64, 32, 64, 36, tid);
  load_tile(sm + SLATH, g_lath + bh * 4096, 64, 32, 64, 36, tid);
  load_tile(sm + SLATL, g_latl + bh * 4096, 64, 32, 64, 36, tid);
  load_tile(sm + SVCH, g_vcth + bh * 4096, 64, 32, 64, 36, tid);
  load_tile(sm + SVCL, g_vctl + bh * 4096, 64, 32, 64, 36, tid);
  size_t tokbase = ((size_t)bh * kN + c * 128) * 64;
  load_tile(sm + TOKH, g_kh + tokbase, 128, 32, 64, 36, tid);
  load_tile(sm + TOKL, g_kl + tokbase, 128, 32, 64, 36, tid);
  __syncthreads();
  float wmix = 1.f / (1.f + __expf(-smx[0]));

  float acc[8][4], out[8][4];
  uint32_t pah[4][4], pal[4][4];

  // ---- self: softmax(K . qg) @ latent ----
  attn_logits(sm + TOKH, sm + TOKL, wid * 16, sm + SQGH, sm + SQGL, 0, acc, g, tg);
  {
    float s0 = 0.f, s1 = 0.f;
#pragma unroll
    for (int nt = 0; nt < 8; nt++) {
      acc[nt][0] = __expf(acc[nt][0]); acc[nt][1] = __expf(acc[nt][1]);
      acc[nt][2] = __expf(acc[nt][2]); acc[nt][3] = __expf(acc[nt][3]);
      s0 += acc[nt][0] + acc[nt][1];
      s1 += acc[nt][2] + acc[nt][3];
    }
    s0 += __shfl_xor_sync(0xffffffffu, s0, 1);
    s0 += __shfl_xor_sync(0xffffffffu, s0, 2);
    s1 += __shfl_xor_sync(0xffffffffu, s1, 1);
    s1 += __shfl_xor_sync(0xffffffffu, s1, 2);
    float w0 = wmix / s0, w1 = wmix / s1;
    pack_p(acc, pah, pal);
    attn_pv(pah, pal, sm + SLATH, sm + SLATL, 36, 0, acc, g, tg);
#pragma unroll
    for (int nt = 0; nt < 8; nt++) {
      out[nt][0] = w0 * acc[nt][0]; out[nt][1] = w0 * acc[nt][1];
      out[nt][2] = w1 * acc[nt][2]; out[nt][3] = w1 * acc[nt][3];
    }
  }

  // swap token tile: K -> Q
  __syncthreads();
  load_tile(sm + TOKH, g_qh + tokbase, 128, 32, 64, 36, tid);
  load_tile(sm + TOKL, g_ql + tokbase, 128, 32, 64, 36, tid);
  __syncthreads();

  // ---- cross: softmax(Q . kc) @ vc ----
  attn_logits(sm + TOKH, sm + TOKL, wid * 16, sm + SKCH, sm + SKCL, 0, acc, g, tg);
  {
    float s0 = 0.f, s1 = 0.f;
#pragma unroll
    for (int nt = 0; nt < 8; nt++) {
      acc[nt][0] = __expf(acc[nt][0]); acc[nt][1] = __expf(acc[nt][1]);
      acc[nt][2] = __expf(acc[nt][2]); acc[nt][3] = __expf(acc[nt][3]);
      s0 += acc[nt][0] + acc[nt][1];
      s1 += acc[nt][2] + acc[nt][3];
    }
    s0 += __shfl_xor_sync(0xffffffffu, s0, 1);
    s0 += __shfl_xor_sync(0xffffffffu, s0, 2);
    s1 += __shfl_xor_sync(0xffffffffu, s1, 1);
    s1 += __shfl_xor_sync(0xffffffffu, s1, 2);
    float w0 = (1.f - wmix) / s0, w1 = (1.f - wmix) / s1;
    pack_p(acc, pah, pal);
    attn_pv(pah, pal, sm + SVCH, sm + SVCL, 36, 0, acc, g, tg);
#pragma unroll
    for (int nt = 0; nt < 8; nt++) {
      out[nt][0] += w0 * acc[nt][0]; out[nt][1] += w0 * acc[nt][1];
      out[nt][2] += w1 * acc[nt][2]; out[nt][3] += w1 * acc[nt][3];
    }
  }

  // write mix hi/lo: row = b*N + tok, col = h*64 + d
  int tok0 = c * 128 + wid * 16 + g;
#pragma unroll
  for (int nt = 0; nt < 8; nt++) {
    int col = h * 64 + nt * 8 + tg * 2;
    size_t a0 = ((size_t)(b * kN + tok0)) * 512 + col;
    uint32_t hi, lo;
    split2(out[nt][0], out[nt][1], hi, lo);
    *(uint32_t*)(g_mixh + a0) = hi;
    *(uint32_t*)(g_mixl + a0) = lo;
    split2(out[nt][2], out[nt][3], hi, lo);
    *(uint32_t*)(g_mixh + a0 + 8 * 512) = hi;
    *(uint32_t*)(g_mixl + a0 + 8 * 512) = lo;
  }
}

// ---------------- launch ----------------
extern "C" void kernel_launch(void* const* d_in, const int* in_sizes, int n_in,
                              void* d_out, int out_size) {
  const float* x    = (const float*)d_in[0];
  const float* ctx  = (const float*)d_in[1];
  const float* qg   = (const float*)d_in[2];
  const float* Wx   = (const float*)d_in[3];
  const float* bx   = (const float*)d_in[4];
  const float* Wk   = (const float*)d_in[5];
  const float* bk   = (const float*)d_in[6];
  const float* Wv   = (const float*)d_in[7];
  const float* bv   = (const float*)d_in[8];
  const float* Wcq  = (const float*)d_in[9];
  const float* bcq  = (const float*)d_in[10];
  const float* Wck  = (const float*)d_in[11];
  const float* bck  = (const float*)d_in[12];
  const float* Wcv  = (const float*)d_in[13];
  const float* bcv  = (const float*)d_in[14];
  const float* smx  = (const float*)d_in[15];
  const float* Wo   = (const float*)d_in[16];
  const float* bo   = (const float*)d_in[17];
  float* out = (float*)d_out;

  void *ahi_p, *alo_p, *whi_p, *wlo_p, *xh_p, *xl_p, *mh_p, *ml_p, *qgh_p, *qgl_p;
  cudaGetSymbolAddress(&ahi_p, g_ahi);
  cudaGetSymbolAddress(&alo_p, g_alo);
  cudaGetSymbolAddress(&whi_p, g_whi);
  cudaGetSymbolAddress(&wlo_p, g_wlo);
  cudaGetSymbolAddress(&xh_p, g_xh);
  cudaGetSymbolAddress(&xl_p, g_xl);
  cudaGetSymbolAddress(&mh_p, g_mixh);
  cudaGetSymbolAddress(&ml_p, g_mixl);
  cudaGetSymbolAddress(&qgh_p, g_qgh);
  cudaGetSymbolAddress(&qgl_p, g_qgl);

  cudaFuncSetAttribute(kvq_mma, cudaFuncAttributeMaxDynamicSharedMemorySize, KVQ_SMEM);
  cudaFuncSetAttribute(enc_mma, cudaFuncAttributeMaxDynamicSharedMemorySize, ENC_SMEM);
  cudaFuncSetAttribute(dec_fused, cudaFuncAttributeMaxDynamicSharedMemorySize, DEC_SMEM);

  const int nA4 = kROWS * kDIM / 4;
  const int nW4 = kDIM * kDIM / 4;

  // proj1: xmid = x @ Wx^T + bx  -> hi/lo
  conv_split<<<nA4 / 256, 256>>>((const float4*)x, (uint2*)ahi_p, (uint2*)alo_p, nA4);
  conv_split<<<nW4 / 256, 256>>>((const float4*)Wx, (uint2*)whi_p, (uint2*)wlo_p, nW4);
  mma512<1><<<dim3(4, kROWS / 128), 256>>>(
      (const uint4*)ahi_p, (const uint4*)alo_p, (const uint4*)whi_p,
      (const uint4*)wlo_p, bx, nullptr, (ushort*)xh_p, (ushort*)xl_p);

  // prep small operands
  prep_wkvq<<<48, 256>>>(Wk, Wv, Wcq);
  conv_split<<<32, 256>>>((const float4*)qg, (uint2*)qgh_p, (uint2*)qgl_p, 8192);
  ctx_proj<<<kBH, 256>>>(ctx, Wck, bck, Wcv, bcv);

  // attention pipeline
  kvq_mma<<<dim3(128, kBH), 256, KVQ_SMEM>>>(bk, bv, bcq);
  enc_mma<<<dim3(128, kBH), 256, ENC_SMEM>>>();
  enc_reduce2<<<dim3(8, kBH), 256>>>();
  dec_fused<<<dim3(128, kBH), 256, DEC_SMEM>>>(smx);

  // proj2: out = mix @ Wo^T + bo
  conv_split<<<nW4 / 256, 256>>>((const float4*)Wo, (uint2*)whi_p, (uint2*)wlo_p, nW4);
  mma512<0><<<dim3(4, kROWS / 128), 256>>>(
      (const uint4*)mh_p, (const uint4*)ml_p, (const uint4*)whi_p,
      (const uint4*)wlo_p, bo, out, nullptr, nullptr);
}

// round 7
// speedup vs baseline: 2.4002x; 1.0747x over previous
#include <cuda_runtime.h>
#include <cuda_bf16.h>
#include <cstdint>

// ---------------- problem constants ----------------
#define kB   2
#define kN   16384
#define kDIM 512
#define kH   8
#define kROWS (kB * kN)          // 32768
#define kBH   (kB * kH)          // 16
#define kSLOTS 256               // enc partial slots (128 chunks x 2 warp-halves)

// ---------------- scratch (device globals) ----------------
__device__ ushort g_xh[kROWS * kDIM],  g_xl[kROWS * kDIM];      // xmid hi/lo
__device__ ushort g_mixh[kROWS * kDIM], g_mixl[kROWS * kDIM];   // gated mix hi/lo
__device__ ushort g_kh[kBH * kN * 64], g_kl[kBH * kN * 64];
__device__ ushort g_qh[kBH * kN * 64], g_ql[kBH * kN * 64];
__device__ ushort g_qgh[512 * 64], g_qgl[512 * 64];             // [h*64+m][d]
__device__ ushort g_kch[kBH * 4096], g_kcl[kBH * 4096];         // [bh][s][d]
__device__ ushort g_vcth[kBH * 4096], g_vctl[kBH * 4096];       // [bh][d][s]
__device__ ushort g_lath[kBH * 4096], g_latl[kBH * 4096];       // latent^T [bh][d][m]
__device__ ushort g_wkvqh[192 * 64], g_wkvql[192 * 64];         // [col(k|v|q)][din]
__device__ ushort g_ahi[kROWS * kDIM], g_alo[kROWS * kDIM];     // proj A split (x)
__device__ ushort g_whi[kDIM * kDIM], g_wlo[kDIM * kDIM];       // proj W split
__device__ float  g_psum[kSLOTS * kBH * 64];
__device__ float  g_pacc[(size_t)kSLOTS * kBH * 4096];          // 67 MB

// ---------------- helpers ----------------
__device__ __forceinline__ ushort bfhi(float x) {
  return __bfloat16_as_ushort(__float2bfloat16(x));
}
__device__ __forceinline__ float bfval(ushort u) {
  return __bfloat162float(__ushort_as_bfloat16(u));
}
__device__ __forceinline__ void split2(float a, float b, uint32_t& hi, uint32_t& lo) {
  ushort ha = bfhi(a), hb = bfhi(b);
  hi = (uint32_t)ha | ((uint32_t)hb << 16);
  lo = (uint32_t)bfhi(a - bfval(ha)) | ((uint32_t)bfhi(b - bfval(hb)) << 16);
}
__device__ __forceinline__ void mma_bf16(float* d, const uint32_t* a,
                                         const uint32_t* b) {
  asm volatile(
      "mma.sync.aligned.m16n8k16.row.col.f32.bf16.bf16.f32 "
      "{%0,%1,%2,%3}, {%4,%5,%6,%7}, {%8,%9}, {%0,%1,%2,%3};"
      : "+f"(d[0]), "+f"(d[1]), "+f"(d[2]), "+f"(d[3])
      : "r"(a[0]), "r"(a[1]), "r"(a[2]), "r"(a[3]), "r"(b[0]), "r"(b[1]));
}
__device__ __forceinline__ uint32_t s2u(const void* p) {
  return (uint32_t)__cvta_generic_to_shared(p);
}
__device__ __forceinline__ void ldsm_x4(uint32_t* r, uint32_t addr) {
  asm volatile(
      "ldmatrix.sync.aligned.m8n8.x4.shared.b16 {%0,%1,%2,%3}, [%4];"
      : "=r"(r[0]), "=r"(r[1]), "=r"(r[2]), "=r"(r[3]) : "r"(addr));
}
// load R rows x (w32 uint32) bf16 tile from gmem into smem with row stride sstr
__device__ __forceinline__ void load_tile(uint32_t* s, const ushort* gp, int rows,
                                          int w32, size_t gstr, int sstr, int tid) {
  int w4 = w32 >> 2;
  for (int idx = tid; idx < rows * w4; idx += 256) {
    int r = idx / w4, w = idx % w4;
    uint4 v = *(const uint4*)(gp + (size_t)r * gstr + w * 8);
    uint32_t* p = s + r * sstr + w * 4;
    p[0] = v.x; p[1] = v.y; p[2] = v.z; p[3] = v.w;
  }
}
__device__ __forceinline__ void lda_f(uint32_t* af, const uint32_t* s, int row,
                                      int ks, int g, int tg, int str) {
  af[0] = s[(row + g) * str + ks * 8 + tg];
  af[1] = s[(row + g + 8) * str + ks * 8 + tg];
  af[2] = s[(row + g) * str + ks * 8 + tg + 4];
  af[3] = s[(row + g + 8) * str + ks * 8 + tg + 4];
}
__device__ __forceinline__ void ldb_f(uint32_t* bf, const uint32_t* s, int col,
                                      int koff, int g, int tg, int str) {
  bf[0] = s[(col + g) * str + koff + tg];
  bf[1] = s[(col + g) * str + koff + tg + 4];
}

// stage1: acc[nt] = Atile(rows arow..+15) x Btile(cols bcol+nt*8), 3-term split
__device__ __forceinline__ void attn_logits(const uint32_t* sAh, const uint32_t* sAl,
                                            int arow, const uint32_t* sBh,
                                            const uint32_t* sBl, int bcol,
                                            float acc[8][4], int g, int tg) {
#pragma unroll
  for (int nt = 0; nt < 8; nt++)
#pragma unroll
    for (int j = 0; j < 4; j++) acc[nt][j] = 0.f;
#pragma unroll
  for (int ks = 0; ks < 4; ks++) {
    uint32_t ah[4], al[4];
    lda_f(ah, sAh, arow, ks, g, tg, 36);
    lda_f(al, sAl, arow, ks, g, tg, 36);
#pragma unroll
    for (int nt = 0; nt < 8; nt++) {
      uint32_t bh2[2], bl2[2];
      ldb_f(bh2, sBh, bcol + nt * 8, ks * 8, g, tg, 36);
      ldb_f(bl2, sBl, bcol + nt * 8, ks * 8, g, tg, 36);
      mma_bf16(acc[nt], ah, bh2);
      mma_bf16(acc[nt], ah, bl2);
      mma_bf16(acc[nt], al, bh2);
    }
  }
}
// pack exp'd probabilities (C frags) into A frags (hi/lo)
__device__ __forceinline__ void pack_p(const float p[8][4], uint32_t pah[4][4],
                                       uint32_t pal[4][4]) {
#pragma unroll
  for (int j = 0; j < 4; j++) {
    split2(p[2 * j][0], p[2 * j][1], pah[j][0], pal[j][0]);
    split2(p[2 * j][2], p[2 * j][3], pah[j][1], pal[j][1]);
    split2(p[2 * j + 1][0], p[2 * j + 1][1], pah[j][2], pal[j][2]);
    split2(p[2 * j + 1][2], p[2 * j + 1][3], pah[j][3], pal[j][3]);
  }
}
// stage2: acc[nt] = P(m16 x k64) x B(cols nt*8, k offset koff), 3-term
__device__ __forceinline__ void attn_pv(const uint32_t pah[4][4],
                                        const uint32_t pal[4][4],
                                        const uint32_t* sBh, const uint32_t* sBl,
                                        int bstr, int koff, float acc[8][4],
                                        int g, int tg) {
#pragma unroll
  for (int nt = 0; nt < 8; nt++)
#pragma unroll
    for (int j = 0; j < 4; j++) acc[nt][j] = 0.f;
#pragma unroll
  for (int ks = 0; ks < 4; ks++) {
#pragma unroll
    for (int nt = 0; nt < 8; nt++) {
      uint32_t bh2[2], bl2[2];
      bh2[0] = sBh[(nt * 8 + g) * bstr + koff + ks * 8 + tg];
      bh2[1] = sBh[(nt * 8 + g) * bstr + koff + ks * 8 + tg + 4];
      bl2[0] = sBl[(nt * 8 + g) * bstr + koff + ks * 8 + tg];
      bl2[1] = sBl[(nt * 8 + g) * bstr + koff + ks * 8 + tg + 4];
      mma_bf16(acc[nt], pah[ks], bh2);
      mma_bf16(acc[nt], pah[ks], bl2);
      mma_bf16(acc[nt], pal[ks], bh2);
    }
  }
}

// ---------------- fp32 -> bf16 hi/lo split (elementwise) ----------------
__global__ __launch_bounds__(256) void conv_split(
    const float4* __restrict__ in, uint2* __restrict__ hi,
    uint2* __restrict__ lo, int n4) {
  int i = blockIdx.x * 256 + threadIdx.x;
  if (i >= n4) return;
  float4 v = in[i];
  uint32_t h0, l0, h1, l1;
  split2(v.x, v.y, h0, l0);
  split2(v.z, v.w, h1, l1);
  hi[i] = make_uint2(h0, h1);
  lo[i] = make_uint2(l0, l1);
}

// ---------------- prep: stacked kvq weights [192][64] hi/lo ----------------
__global__ __launch_bounds__(256) void prep_wkvq(const float* __restrict__ Wk,
                                                 const float* __restrict__ Wv,
                                                 const float* __restrict__ Wq) {
  int i = blockIdx.x * 256 + threadIdx.x;
  if (i >= 192 * 64) return;
  int r = i >> 6, cin = i & 63;
  float w = (r < 64) ? Wk[r * 64 + cin]
            : (r < 128) ? Wv[(r - 64) * 64 + cin] : Wq[(r - 128) * 64 + cin];
  ushort h = bfhi(w);
  g_wkvqh[i] = h;
  g_wkvql[i] = bfhi(w - bfval(h));
}

// ---------------- ctx: kc [bh][s][d], vcT [bh][d][s] hi/lo ----------------
__global__ __launch_bounds__(256) void ctx_proj(
    const float* __restrict__ context, const float* __restrict__ Wck,
    const float* __restrict__ bck, const float* __restrict__ Wcv,
    const float* __restrict__ bcv) {
  __shared__ float sctx[64 * 64];
  int tid = threadIdx.x, bh = blockIdx.x;
  for (int idx = tid; idx < 4096; idx += 256)
    sctx[idx] = context[(size_t)bh * 4096 + idx];
  __syncthreads();
  for (int t = tid; t < 8192; t += 256) {
    int sel = t >> 12;
    int r = t & 4095;
    int s = r >> 6, d = r & 63;
    const float* W = sel ? Wcv : Wck;
    float acc = sel ? bcv[d] : bck[d];
#pragma unroll 8
    for (int c = 0; c < 64; c++) acc += sctx[s * 64 + c] * W[d * 64 + c];
    ushort h = bfhi(acc), l = bfhi(acc - bfval(h));
    if (sel == 0) {
      g_kch[bh * 4096 + s * 64 + d] = h;
      g_kcl[bh * 4096 + s * 64 + d] = l;
    } else {
      g_vcth[bh * 4096 + d * 64 + s] = h;
      g_vctl[bh * 4096 + d * 64 + s] = l;
    }
  }
}

// ---------------- proj GEMM: C = A(32768x512) @ W(512x512)^T + bias ----------------
#define SA_STRIDE 20
template <int SPLITOUT>
__global__ __launch_bounds__(256) void mma512(
    const uint4* __restrict__ Ahi, const uint4* __restrict__ Alo,
    const uint4* __restrict__ Bhi, const uint4* __restrict__ Blo,
    const float* __restrict__ bias, float* __restrict__ C,
    ushort* __restrict__ Ch, ushort* __restrict__ Cl) {
  __shared__ uint32_t sA[2][128][SA_STRIDE];
  __shared__ uint32_t sB[2][128][SA_STRIDE];
  int tid = threadIdx.x, wid = tid >> 5, lane = tid & 31;
  int wr = wid >> 1, wc = wid & 1;
  int g = lane >> 2, tg = lane & 3;
  size_t br = (size_t)blockIdx.y * 128;
  int bc = blockIdx.x * 128;

  float acc[2][8][4];
#pragma unroll
  for (int mt = 0; mt < 2; mt++)
#pragma unroll
    for (int nt = 0; nt < 8; nt++)
#pragma unroll
      for (int j = 0; j < 4; j++) acc[mt][nt][j] = 0.f;

  // ldmatrix lane addressing
  int a_row = lane & 15, a_w = (lane >> 4) * 4;
  int b_row = ((lane >> 4) << 3) + (lane & 7), b_w = ((lane >> 3) & 1) * 4;

  uint4 pre[2][4];
#pragma unroll
  for (int i = 0; i < 2; i++) {
    int idx = tid + i * 256;
    int r = idx >> 2, c4 = idx & 3;
    size_t ga = (br + r) * 64 + c4;
    size_t gb = ((size_t)bc + r) * 64 + c4;
    pre[i][0] = Ahi[ga]; pre[i][1] = Alo[ga];
    pre[i][2] = Bhi[gb]; pre[i][3] = Blo[gb];
  }

  for (int kc = 0; kc < 16; kc++) {
    __syncthreads();
#pragma unroll
    for (int i = 0; i < 2; i++) {
      int idx = tid + i * 256;
      int r = idx >> 2, c4 = idx & 3;
      uint32_t* pa0 = &sA[0][r][c4 * 4];
      uint32_t* pa1 = &sA[1][r][c4 * 4];
      uint32_t* pb0 = &sB[0][r][c4 * 4];
      uint32_t* pb1 = &sB[1][r][c4 * 4];
      pa0[0] = pre[i][0].x; pa0[1] = pre[i][0].y; pa0[2] = pre[i][0].z; pa0[3] = pre[i][0].w;
      pa1[0] = pre[i][1].x; pa1[1] = pre[i][1].y; pa1[2] = pre[i][1].z; pa1[3] = pre[i][1].w;
      pb0[0] = pre[i][2].x; pb0[1] = pre[i][2].y; pb0[2] = pre[i][2].z; pb0[3] = pre[i][2].w;
      pb1[0] = pre[i][3].x; pb1[1] = pre[i][3].y; pb1[2] = pre[i][3].z; pb1[3] = pre[i][3].w;
    }
    __syncthreads();
    if (kc < 15) {
#pragma unroll
      for (int i = 0; i < 2; i++) {
        int idx = tid + i * 256;
        int r = idx >> 2, c4 = idx & 3;
        size_t ga = (br + r) * 64 + (kc + 1) * 4 + c4;
        size_t gb = ((size_t)bc + r) * 64 + (kc + 1) * 4 + c4;
        pre[i][0] = Ahi[ga]; pre[i][1] = Alo[ga];
        pre[i][2] = Bhi[gb]; pre[i][3] = Blo[gb];
      }
    }
#pragma unroll
    for (int ks = 0; ks < 2; ks++) {
      uint32_t af[2][2][4];
#pragma unroll
      for (int h = 0; h < 2; h++)
#pragma unroll
        for (int mt = 0; mt < 2; mt++) {
          int row = wr * 32 + mt * 16 + a_row;
          ldsm_x4(af[h][mt], s2u(&sA[h][row][ks * 8 + a_w]));
        }
      uint32_t bfr[2][8][2];
#pragma unroll
      for (int h = 0; h < 2; h++)
#pragma unroll
        for (int ntp = 0; ntp < 4; ntp++) {
          uint32_t bq[4];
          int col = wc * 64 + ntp * 16 + b_row;
          ldsm_x4(bq, s2u(&sB[h][col][ks * 8 + b_w]));
          bfr[h][ntp * 2][0] = bq[0]; bfr[h][ntp * 2][1] = bq[1];
          bfr[h][ntp * 2 + 1][0] = bq[2]; bfr[h][ntp * 2 + 1][1] = bq[3];
        }
#pragma unroll
      for (int mt = 0; mt < 2; mt++)
#pragma unroll
        for (int nt = 0; nt < 8; nt++) {
          mma_bf16(acc[mt][nt], af[0][mt], bfr[0][nt]);
          mma_bf16(acc[mt][nt], af[0][mt], bfr[1][nt]);
          mma_bf16(acc[mt][nt], af[1][mt], bfr[0][nt]);
        }
    }
  }

#pragma unroll
  for (int mt = 0; mt < 2; mt++) {
    size_t row0 = br + wr * 32 + mt * 16 + g;
#pragma unroll
    for (int nt = 0; nt < 8; nt++) {
      int col = bc + wc * 64 + nt * 8 + tg * 2;
      float bx0 = bias[col], bx1 = bias[col + 1];
      float v0 = acc[mt][nt][0] + bx0, v1 = acc[mt][nt][1] + bx1;
      float v2 = acc[mt][nt][2] + bx0, v3 = acc[mt][nt][3] + bx1;
      if (SPLITOUT) {
        uint32_t hi, lo;
        split2(v0, v1, hi, lo);
        *(uint32_t*)(Ch + row0 * 512 + col) = hi;
        *(uint32_t*)(Cl + row0 * 512 + col) = lo;
        split2(v2, v3, hi, lo);
        *(uint32_t*)(Ch + (row0 + 8) * 512 + col) = hi;
        *(uint32_t*)(Cl + (row0 + 8) * 512 + col) = lo;
      } else {
        *(float2*)&C[row0 * 512 + col] = make_float2(v0, v1);
        *(float2*)&C[(row0 + 8) * 512 + col] = make_float2(v2, v3);
      }
    }
  }
}

// ---------------- fused KVQ + encode: V never leaves the CTA ----------------
#define FXA_H 0
#define FXA_L 4608
#define FW_H  9216
#define FW_L  16128
#define FK_H  0
#define FK_L  4608
#define FVT_H 9216
#define FVT_L 13568
#define FQG_H 17920
#define FQG_L 20224
#define KVQENC_SMEM (23040 * 4)
__global__ __launch_bounds__(256) void kvqenc(const float* __restrict__ bk,
                                              const float* __restrict__ bv,
                                              const float* __restrict__ bq) {
  extern __shared__ uint32_t sm[];
  int tid = threadIdx.x, wid = tid >> 5, lane = tid & 31;
  int g = lane >> 2, tg = lane & 3;
  int wr = wid >> 1, wc = wid & 1;
  int c = blockIdx.x, bh = blockIdx.y, h = bh & 7, b = bh >> 3;

  // ---- phase A: kvq GEMM ----
  size_t abase = ((size_t)(b * kN + c * 128)) * 512 + h * 64;
  load_tile(sm + FXA_H, g_xh + abase, 128, 32, 512, 36, tid);
  load_tile(sm + FXA_L, g_xl + abase, 128, 32, 512, 36, tid);
  load_tile(sm + FW_H, g_wkvqh, 192, 32, 64, 36, tid);
  load_tile(sm + FW_L, g_wkvql, 192, 32, 64, 36, tid);
  __syncthreads();

  float kacc[2][12][4];
#pragma unroll
  for (int mt = 0; mt < 2; mt++)
#pragma unroll
    for (int nt = 0; nt < 12; nt++)
#pragma unroll
      for (int j = 0; j < 4; j++) kacc[mt][nt][j] = 0.f;

#pragma unroll
  for (int ks = 0; ks < 4; ks++) {
    uint32_t ah[2][4], al[2][4];
#pragma unroll
    for (int mt = 0; mt < 2; mt++) {
      lda_f(ah[mt], sm + FXA_H, wr * 32 + mt * 16, ks, g, tg, 36);
      lda_f(al[mt], sm + FXA_L, wr * 32 + mt * 16, ks, g, tg, 36);
    }
#pragma unroll
    for (int nt = 0; nt < 12; nt++) {
      uint32_t bh2[2], bl2[2];
      ldb_f(bh2, sm + FW_H, wc * 96 + nt * 8, ks * 8, g, tg, 36);
      ldb_f(bl2, sm + FW_L, wc * 96 + nt * 8, ks * 8, g, tg, 36);
#pragma unroll
      for (int mt = 0; mt < 2; mt++) {
        mma_bf16(kacc[mt][nt], ah[mt], bh2);
        mma_bf16(kacc[mt][nt], ah[mt], bl2);
        mma_bf16(kacc[mt][nt], al[mt], bh2);
      }
    }
  }
  __syncthreads();  // phase A smem dead; overlay phase B

  // ---- stage K/V into smem, write K/Q to gmem ----
  ushort* svth = (ushort*)(sm + FVT_H);  // [64 d][136]
  ushort* svtl = (ushort*)(sm + FVT_L);
#pragma unroll
  for (int mt = 0; mt < 2; mt++) {
    int tl = wr * 32 + mt * 16 + g;       // local token 0..127
    int tok = c * 128 + tl;
#pragma unroll
    for (int nt = 0; nt < 12; nt++) {
      int col = wc * 96 + nt * 8 + tg * 2;
      int sel = col >> 6, d = col & 63;
      float b0 = (sel == 0) ? bk[d] : (sel == 1) ? bv[d] : bq[d];
      float b1 = (sel == 0) ? bk[d + 1] : (sel == 1) ? bv[d + 1] : bq[d + 1];
      float v0 = kacc[mt][nt][0] + b0, v1 = kacc[mt][nt][1] + b1;
      float v2 = kacc[mt][nt][2] + b0, v3 = kacc[mt][nt][3] + b1;
      if (sel == 1) {                     // V -> smem transposed only
        ushort hh;
        hh = bfhi(v0); svth[d * 136 + tl] = hh;             svtl[d * 136 + tl] = bfhi(v0 - bfval(hh));
        hh = bfhi(v2); svth[d * 136 + tl + 8] = hh;         svtl[d * 136 + tl + 8] = bfhi(v2 - bfval(hh));
        hh = bfhi(v1); svth[(d + 1) * 136 + tl] = hh;       svtl[(d + 1) * 136 + tl] = bfhi(v1 - bfval(hh));
        hh = bfhi(v3); svth[(d + 1) * 136 + tl + 8] = hh;   svtl[(d + 1) * 136 + tl + 8] = bfhi(v3 - bfval(hh));
      } else {
        uint32_t hi, lo, hi2, lo2;
        split2(v0, v1, hi, lo);
        split2(v2, v3, hi2, lo2);
        if (sel == 0) {                   // K -> smem [tok][d] + gmem
          sm[FK_H + tl * 36 + (col >> 1)] = hi;
          sm[FK_L + tl * 36 + (col >> 1)] = lo;
          sm[FK_H + (tl + 8) * 36 + (col >> 1)] = hi2;
          sm[FK_L + (tl + 8) * 36 + (col >> 1)] = lo2;
        }
        ushort* oh = (sel == 0) ? g_kh : g_qh;
        ushort* ol = (sel == 0) ? g_kl : g_ql;
        size_t ob = ((size_t)bh * kN + tok) * 64 + d;
        *(uint32_t*)(oh + ob) = hi; *(uint32_t*)(ol + ob) = lo;
        *(uint32_t*)(oh + ob + 8 * 64) = hi2; *(uint32_t*)(ol + ob + 8 * 64) = lo2;
      }
    }
  }
  load_tile(sm + FQG_H, g_qgh + h * 4096, 64, 32, 64, 36, tid);
  load_tile(sm + FQG_L, g_qgl + h * 4096, 64, 32, 64, 36, tid);
  __syncthreads();

  // ---- phase B: encode logits + P@V ----
  float acc[8][4];
  attn_logits(sm + FQG_H, sm + FQG_L, wr * 16, sm + FK_H, sm + FK_L, wc * 64,
              acc, g, tg);
  float s0 = 0.f, s1 = 0.f;
#pragma unroll
  for (int nt = 0; nt < 8; nt++) {
    acc[nt][0] = __expf(acc[nt][0]); acc[nt][1] = __expf(acc[nt][1]);
    acc[nt][2] = __expf(acc[nt][2]); acc[nt][3] = __expf(acc[nt][3]);
    s0 += acc[nt][0] + acc[nt][1];
    s1 += acc[nt][2] + acc[nt][3];
  }
  s0 += __shfl_xor_sync(0xffffffffu, s0, 1);
  s0 += __shfl_xor_sync(0xffffffffu, s0, 2);
  s1 += __shfl_xor_sync(0xffffffffu, s1, 1);
  s1 += __shfl_xor_sync(0xffffffffu, s1, 2);
  int slot = c * 2 + wc;
  if (tg == 0) {
    size_t pb = ((size_t)slot * kBH + bh) * 64 + wr * 16 + g;
    g_psum[pb] = s0;
    g_psum[pb + 8] = s1;
  }
  uint32_t pah[4][4], pal[4][4];
  pack_p(acc, pah, pal);
  attn_pv(pah, pal, sm + FVT_H, sm + FVT_L, 68, wc * 32, acc, g, tg);
  size_t ab = ((size_t)slot * kBH + bh) * 4096 + (wr * 16 + g) * 64;
#pragma unroll
  for (int nt = 0; nt < 8; nt++) {
    int d = nt * 8 + tg * 2;
    *(float2*)&g_pacc[ab + d] = make_float2(acc[nt][0], acc[nt][1]);
    *(float2*)&g_pacc[ab + 8 * 64 + d] = make_float2(acc[nt][2], acc[nt][3]);
  }
}

// ---------------- encode reduce -> latent^T hi/lo ----------------
__global__ __launch_bounds__(256) void enc_reduce2() {
  __shared__ float sinv[64];
  int tid = threadIdx.x;
  int dchunk = blockIdx.x, bh = blockIdx.y;
  if (tid < 64) {
    float s = 0.f;
    for (int s2 = 0; s2 < kSLOTS; s2++)
      s += g_psum[((size_t)s2 * kBH + bh) * 64 + tid];
    sinv[tid] = 1.f / s;
  }
  __syncthreads();
  for (int idx = tid; idx < 512; idx += 256) {
    int e = dchunk * 512 + idx;
    int m = e >> 6, d = e & 63;
    float a = 0.f;
    for (int s2 = 0; s2 < kSLOTS; s2++)
      a += g_pacc[((size_t)s2 * kBH + bh) * 4096 + e];
    float v = a * sinv[m];
    ushort hh = bfhi(v);
    g_lath[bh * 4096 + d * 64 + m] = hh;
    g_latl[bh * 4096 + d * 64 + m] = bfhi(v - bfval(hh));
  }
}

// ---------------- fused decode-self + cross + gate -> mix hi/lo ----------------
#define TOKH 0
#define TOKL 4608
#define SQGH 9216
#define SQGL 11520
#define SKCH 13824
#define SKCL 16128
#define SLATH 18432
#define SLATL 20736
#define SVCH 23040
#define SVCL 25344
#define DEC_SMEM (27648 * 4)
__global__ __launch_bounds__(256) void dec_fused(const float* __restrict__ smx) {
  extern __shared__ uint32_t sm[];
  int tid = threadIdx.x, wid = tid >> 5, lane = tid & 31;
  int g = lane >> 2, tg = lane & 3;
  int c = blockIdx.x, bh = blockIdx.y, h = bh & 7, b = bh >> 3;
  load_tile(sm + SQGH, g_qgh + h * 4096, 64, 32, 64, 36, tid);
  load_tile(sm + SQGL, g_qgl + h * 4096, 64, 32, 64, 36, tid);
  load_tile(sm + SKCH, g_kch + bh * 4096, 64, 32, 64, 36, tid);
  load_tile(sm + SKCL, g_kcl + bh * 4096, 64, 32, 64, 36, tid);
  load_tile(sm + SLATH, g_lath + bh * 4096, 64, 32, 64, 36, tid);
  load_tile(sm + SLATL, g_latl + bh * 4096, 64, 32, 64, 36, tid);
  load_tile(sm + SVCH, g_vcth + bh * 4096, 64, 32, 64, 36, tid);
  load_tile(sm + SVCL, g_vctl + bh * 4096, 64, 32, 64, 36, tid);
  size_t tokbase = ((size_t)bh * kN + c * 128) * 64;
  load_tile(sm + TOKH, g_kh + tokbase, 128, 32, 64, 36, tid);
  load_tile(sm + TOKL, g_kl + tokbase, 128, 32, 64, 36, tid);
  __syncthreads();
  float wmix = 1.f / (1.f + __expf(-smx[0]));

  float acc[8][4], out[8][4];
  uint32_t pah[4][4], pal[4][4];

  // ---- self: softmax(K . qg) @ latent ----
  attn_logits(sm + TOKH, sm + TOKL, wid * 16, sm + SQGH, sm + SQGL, 0, acc, g, tg);
  {
    float s0 = 0.f, s1 = 0.f;
#pragma unroll
    for (int nt = 0; nt < 8; nt++) {
      acc[nt][0] = __expf(acc[nt][0]); acc[nt][1] = __expf(acc[nt][1]);
      acc[nt][2] = __expf(acc[nt][2]); acc[nt][3] = __expf(acc[nt][3]);
      s0 += acc[nt][0] + acc[nt][1];
      s1 += acc[nt][2] + acc[nt][3];
    }
    s0 += __shfl_xor_sync(0xffffffffu, s0, 1);
    s0 += __shfl_xor_sync(0xffffffffu, s0, 2);
    s1 += __shfl_xor_sync(0xffffffffu, s1, 1);
    s1 += __shfl_xor_sync(0xffffffffu, s1, 2);
    float w0 = wmix / s0, w1 = wmix / s1;
    pack_p(acc, pah, pal);
    attn_pv(pah, pal, sm + SLATH, sm + SLATL, 36, 0, acc, g, tg);
#pragma unroll
    for (int nt = 0; nt < 8; nt++) {
      out[nt][0] = w0 * acc[nt][0]; out[nt][1] = w0 * acc[nt][1];
      out[nt][2] = w1 * acc[nt][2]; out[nt][3] = w1 * acc[nt][3];
    }
  }

  // swap token tile: K -> Q
  __syncthreads();
  load_tile(sm + TOKH, g_qh + tokbase, 128, 32, 64, 36, tid);
  load_tile(sm + TOKL, g_ql + tokbase, 128, 32, 64, 36, tid);
  __syncthreads();

  // ---- cross: softmax(Q . kc) @ vc ----
  attn_logits(sm + TOKH, sm + TOKL, wid * 16, sm + SKCH, sm + SKCL, 0, acc, g, tg);
  {
    float s0 = 0.f, s1 = 0.f;
#pragma unroll
    for (int nt = 0; nt < 8; nt++) {
      acc[nt][0] = __expf(acc[nt][0]); acc[nt][1] = __expf(acc[nt][1]);
      acc[nt][2] = __expf(acc[nt][2]); acc[nt][3] = __expf(acc[nt][3]);
      s0 += acc[nt][0] + acc[nt][1];
      s1 += acc[nt][2] + acc[nt][3];
    }
    s0 += __shfl_xor_sync(0xffffffffu, s0, 1);
    s0 += __shfl_xor_sync(0xffffffffu, s0, 2);
    s1 += __shfl_xor_sync(0xffffffffu, s1, 1);
    s1 += __shfl_xor_sync(0xffffffffu, s1, 2);
    float w0 = (1.f - wmix) / s0, w1 = (1.f - wmix) / s1;
    pack_p(acc, pah, pal);
    attn_pv(pah, pal, sm + SVCH, sm + SVCL, 36, 0, acc, g, tg);
#pragma unroll
    for (int nt = 0; nt < 8; nt++) {
      out[nt][0] += w0 * acc[nt][0]; out[nt][1] += w0 * acc[nt][1];
      out[nt][2] += w1 * acc[nt][2]; out[nt][3] += w1 * acc[nt][3];
    }
  }

  // write mix hi/lo
  int tok0 = c * 128 + wid * 16 + g;
#pragma unroll
  for (int nt = 0; nt < 8; nt++) {
    int col = h * 64 + nt * 8 + tg * 2;
    size_t a0 = ((size_t)(b * kN + tok0)) * 512 + col;
    uint32_t hi, lo;
    split2(out[nt][0], out[nt][1], hi, lo);
    *(uint32_t*)(g_mixh + a0) = hi;
    *(uint32_t*)(g_mixl + a0) = lo;
    split2(out[nt][2], out[nt][3], hi, lo);
    *(uint32_t*)(g_mixh + a0 + 8 * 512) = hi;
    *(uint32_t*)(g_mixl + a0 + 8 * 512) = lo;
  }
}

// ---------------- launch ----------------
extern "C" void kernel_launch(void* const* d_in, const int* in_sizes, int n_in,
                              void* d_out, int out_size) {
  const float* x    = (const float*)d_in[0];
  const float* ctx  = (const float*)d_in[1];
  const float* qg   = (const float*)d_in[2];
  const float* Wx   = (const float*)d_in[3];
  const float* bx   = (const float*)d_in[4];
  const float* Wk   = (const float*)d_in[5];
  const float* bk   = (const float*)d_in[6];
  const float* Wv   = (const float*)d_in[7];
  const float* bv   = (const float*)d_in[8];
  const float* Wcq  = (const float*)d_in[9];
  const float* bcq  = (const float*)d_in[10];
  const float* Wck  = (const float*)d_in[11];
  const float* bck  = (const float*)d_in[12];
  const float* Wcv  = (const float*)d_in[13];
  const float* bcv  = (const float*)d_in[14];
  const float* smx  = (const float*)d_in[15];
  const float* Wo   = (const float*)d_in[16];
  const float* bo   = (const float*)d_in[17];
  float* out = (float*)d_out;

  void *ahi_p, *alo_p, *whi_p, *wlo_p, *xh_p, *xl_p, *mh_p, *ml_p, *qgh_p, *qgl_p;
  cudaGetSymbolAddress(&ahi_p, g_ahi);
  cudaGetSymbolAddress(&alo_p, g_alo);
  cudaGetSymbolAddress(&whi_p, g_whi);
  cudaGetSymbolAddress(&wlo_p, g_wlo);
  cudaGetSymbolAddress(&xh_p, g_xh);
  cudaGetSymbolAddress(&xl_p, g_xl);
  cudaGetSymbolAddress(&mh_p, g_mixh);
  cudaGetSymbolAddress(&ml_p, g_mixl);
  cudaGetSymbolAddress(&qgh_p, g_qgh);
  cudaGetSymbolAddress(&qgl_p, g_qgl);

  cudaFuncSetAttribute(kvqenc, cudaFuncAttributeMaxDynamicSharedMemorySize,
                       KVQENC_SMEM);
  cudaFuncSetAttribute(dec_fused, cudaFuncAttributeMaxDynamicSharedMemorySize,
                       DEC_SMEM);

  const int nA4 = kROWS * kDIM / 4;
  const int nW4 = kDIM * kDIM / 4;

  // proj1: xmid = x @ Wx^T + bx  -> hi/lo
  conv_split<<<nA4 / 256, 256>>>((const float4*)x, (uint2*)ahi_p, (uint2*)alo_p, nA4);
  conv_split<<<nW4 / 256, 256>>>((const float4*)Wx, (uint2*)whi_p, (uint2*)wlo_p, nW4);
  mma512<1><<<dim3(4, kROWS / 128), 256>>>(
      (const uint4*)ahi_p, (const uint4*)alo_p, (const uint4*)whi_p,
      (const uint4*)wlo_p, bx, nullptr, (ushort*)xh_p, (ushort*)xl_p);

  // prep small operands
  prep_wkvq<<<48, 256>>>(Wk, Wv, Wcq);
  conv_split<<<32, 256>>>((const float4*)qg, (uint2*)qgh_p, (uint2*)qgl_p, 8192);
  ctx_proj<<<kBH, 256>>>(ctx, Wck, bck, Wcv, bcv);

  // fused kvq + encode, then reduce, then fused decode
  kvqenc<<<dim3(128, kBH), 256, KVQENC_SMEM>>>(bk, bv, bcq);
  enc_reduce2<<<dim3(8, kBH), 256>>>();
  dec_fused<<<dim3(128, kBH), 256, DEC_SMEM>>>(smx);

  // proj2: out = mix @ Wo^T + bo
  conv_split<<<nW4 / 256, 256>>>((const float4*)Wo, (uint2*)whi_p, (uint2*)wlo_p, nW4);
  mma512<0><<<dim3(4, kROWS / 128), 256>>>(
      (const uint4*)mh_p, (const uint4*)ml_p, (const uint4*)whi_p,
      (const uint4*)wlo_p, bo, out, nullptr, nullptr);
}